// round 1
// baseline (speedup 1.0000x reference)
#include <cuda_runtime.h>
#include <math.h>
#include <stdint.h>

// Problem constants
constexpr int B_  = 4;
constexpr int T_  = 2048;
constexpr int C_  = 1024;
constexpr int H_  = 16;
constexpr int HD  = 64;          // head dim
constexpr int M_  = B_ * T_;     // 8192 rows for projections

// -------------------- scratch (static device allocations) --------------------
__device__ float g_q[B_ * H_ * T_ * HD];    // [B,H,T,hd]
__device__ float g_k[B_ * H_ * T_ * HD];
__device__ float g_v[B_ * H_ * T_ * HD];
__device__ float g_att[B_ * T_ * C_];       // [B,T,C] attention output (pre-proj)

// =============================================================================
// GEMM: out = A[M,K] @ W[N,K]^T + bias[N]
// OUT_MODE 0: out row-major [M,N]
// OUT_MODE 1: out scattered to [B,H,T,hd]  (m=b*T+t, n=h*64+d)
// BM=BN=128, BK=16, 256 threads, 8x8 microtile.
// =============================================================================
template <int OUT_MODE>
__global__ __launch_bounds__(256) void gemm_bias_kernel(
    const float* __restrict__ A, const float* __restrict__ W,
    const float* __restrict__ bias, float* __restrict__ out)
{
    constexpr int BM = 128, BN = 128, BK = 16;
    __shared__ __align__(16) float As[BK][BM];
    __shared__ __align__(16) float Ws[BK][BN];

    const int tid = threadIdx.x;
    const int tx  = tid & 15;     // n-direction
    const int ty  = tid >> 4;     // m-direction
    const int bm  = blockIdx.y * BM;
    const int bn  = blockIdx.x * BN;
    const int K   = C_;

    float acc[8][8];
    #pragma unroll
    for (int i = 0; i < 8; i++)
        #pragma unroll
        for (int j = 0; j < 8; j++) acc[i][j] = 0.f;

    for (int k0 = 0; k0 < K; k0 += BK) {
        // Load 128x16 tiles of A and W, transposed into smem ([k][m]).
        // id -> row = id>>2, c4 = (id&3)*4 : coalesced 64B/8-row global reads.
        #pragma unroll
        for (int it = 0; it < 2; it++) {
            int id  = tid + it * 256;
            int row = id >> 2;
            int c4  = (id & 3) * 4;
            float4 av = *(const float4*)&A[(size_t)(bm + row) * K + k0 + c4];
            As[c4 + 0][row] = av.x; As[c4 + 1][row] = av.y;
            As[c4 + 2][row] = av.z; As[c4 + 3][row] = av.w;
            float4 wv = *(const float4*)&W[(size_t)(bn + row) * K + k0 + c4];
            Ws[c4 + 0][row] = wv.x; Ws[c4 + 1][row] = wv.y;
            Ws[c4 + 2][row] = wv.z; Ws[c4 + 3][row] = wv.w;
        }
        __syncthreads();

        #pragma unroll
        for (int kk = 0; kk < BK; kk++) {
            float4 a0 = *(const float4*)&As[kk][ty * 8];
            float4 a1 = *(const float4*)&As[kk][ty * 8 + 4];
            float4 b0 = *(const float4*)&Ws[kk][tx * 8];
            float4 b1 = *(const float4*)&Ws[kk][tx * 8 + 4];
            float a[8] = {a0.x, a0.y, a0.z, a0.w, a1.x, a1.y, a1.z, a1.w};
            float b[8] = {b0.x, b0.y, b0.z, b0.w, b1.x, b1.y, b1.z, b1.w};
            #pragma unroll
            for (int i = 0; i < 8; i++)
                #pragma unroll
                for (int j = 0; j < 8; j++)
                    acc[i][j] = fmaf(a[i], b[j], acc[i][j]);
        }
        __syncthreads();
    }

    // Epilogue: bias + store (vectorized, 4-contiguous in n)
    #pragma unroll
    for (int i = 0; i < 8; i++) {
        int m = bm + ty * 8 + i;
        #pragma unroll
        for (int jj = 0; jj < 2; jj++) {
            int n = bn + tx * 8 + jj * 4;
            float4 bv = *(const float4*)&bias[n];
            float4 r;
            r.x = acc[i][jj * 4 + 0] + bv.x;
            r.y = acc[i][jj * 4 + 1] + bv.y;
            r.z = acc[i][jj * 4 + 2] + bv.z;
            r.w = acc[i][jj * 4 + 3] + bv.w;
            if (OUT_MODE == 0) {
                *(float4*)&out[(size_t)m * C_ + n] = r;
            } else {
                int b = m / T_, t = m - b * T_;
                int h = n >> 6, d = n & 63;
                *(float4*)&out[(((size_t)(b * H_ + h) * T_ + t) * HD) + d] = r;
            }
        }
    }
}

// =============================================================================
// Flash attention (causal): one CTA per (b*H+h, q-tile of 64).
// Q,K,V: [B,H,T,hd] fp32.  Output: [B,T,C] ([t][h*64+d]).
// 256 threads, 4x4 microtiles for S (64x64) and O (64x64).
// =============================================================================
constexpr int BQ  = 64;
constexpr int BKT = 64;
constexpr int SP  = 68;                 // padded Ss row stride
constexpr int SMEM_ATT_FLOATS =
    HD * BQ      // Qs [d][r]
  + HD * BKT     // Ks [d][c]
  + BKT * HD     // Vs [c][d]
  + BQ * SP      // Ss
  + 3 * BQ;      // m, l, alpha
constexpr int SMEM_ATT_BYTES = SMEM_ATT_FLOATS * 4;

__global__ __launch_bounds__(256) void attn_kernel(
    const float* __restrict__ Q, const float* __restrict__ K,
    const float* __restrict__ V, float* __restrict__ out)
{
    extern __shared__ __align__(16) float sm[];
    float* Qs  = sm;                          // [HD][BQ]
    float* Ks  = Qs + HD * BQ;                // [HD][BKT]
    float* Vs  = Ks + HD * BKT;               // [BKT][HD]
    float* Ss  = Vs + BKT * HD;               // [BQ][SP]
    float* m_s = Ss + BQ * SP;
    float* l_s = m_s + BQ;
    float* al_s = l_s + BQ;

    const int tid = threadIdx.x;
    const int tx  = tid & 15;    // k-col / d-col direction
    const int ty  = tid >> 4;    // q-row direction
    const int bh  = blockIdx.x;  // b*H + h
    const int qi  = blockIdx.y;
    const int q0  = qi * BQ;

    const float* Qb = Q + (size_t)bh * T_ * HD;
    const float* Kb = K + (size_t)bh * T_ * HD;
    const float* Vb = V + (size_t)bh * T_ * HD;

    // Load Q tile transposed: Qs[d][r]. Column-major lane map -> conflict-free STS.
    #pragma unroll
    for (int it = 0; it < 4; it++) {
        int id = tid + it * 256;
        int r  = id & 63;
        int c4 = (id >> 6) * 4;
        float4 qv = *(const float4*)&Qb[(size_t)(q0 + r) * HD + c4];
        Qs[(c4 + 0) * BQ + r] = qv.x; Qs[(c4 + 1) * BQ + r] = qv.y;
        Qs[(c4 + 2) * BQ + r] = qv.z; Qs[(c4 + 3) * BQ + r] = qv.w;
    }
    if (tid < BQ) { m_s[tid] = -3.0e38f; l_s[tid] = 0.f; }

    float o[4][4];
    #pragma unroll
    for (int i = 0; i < 4; i++)
        #pragma unroll
        for (int j = 0; j < 4; j++) o[i][j] = 0.f;

    __syncthreads();

    for (int kt = 0; kt <= qi; kt++) {
        const int k0 = kt * BKT;
        // Load K transposed (Ks[d][c]), V natural (Vs[c][d]).
        #pragma unroll
        for (int it = 0; it < 4; it++) {
            int id = tid + it * 256;
            {   // K transposed, column-major lane map
                int r  = id & 63;
                int c4 = (id >> 6) * 4;
                float4 kv = *(const float4*)&Kb[(size_t)(k0 + r) * HD + c4];
                Ks[(c4 + 0) * BKT + r] = kv.x; Ks[(c4 + 1) * BKT + r] = kv.y;
                Ks[(c4 + 2) * BKT + r] = kv.z; Ks[(c4 + 3) * BKT + r] = kv.w;
            }
            {   // V natural, coalesced both ways
                int r  = id >> 4;
                int c4 = (id & 15) * 4;
                float4 vv = *(const float4*)&Vb[(size_t)(k0 + r) * HD + c4];
                *(float4*)&Vs[r * HD + c4] = vv;
            }
        }
        __syncthreads();

        // S = Q @ K^T : outer product over d
        float s[4][4];
        #pragma unroll
        for (int i = 0; i < 4; i++)
            #pragma unroll
            for (int j = 0; j < 4; j++) s[i][j] = 0.f;

        #pragma unroll 8
        for (int d = 0; d < HD; d++) {
            float4 qf = *(const float4*)&Qs[d * BQ + ty * 4];
            float4 kf = *(const float4*)&Ks[d * BKT + tx * 4];
            float qa[4] = {qf.x, qf.y, qf.z, qf.w};
            float ka[4] = {kf.x, kf.y, kf.z, kf.w};
            #pragma unroll
            for (int i = 0; i < 4; i++)
                #pragma unroll
                for (int j = 0; j < 4; j++)
                    s[i][j] = fmaf(qa[i], ka[j], s[i][j]);
        }

        // scale + causal mask, write to Ss
        const bool diag = (kt == qi);
        #pragma unroll
        for (int i = 0; i < 4; i++) {
            int r = ty * 4 + i;
            #pragma unroll
            for (int j = 0; j < 4; j++) {
                int cc = tx * 4 + j;
                float val = s[i][j] * 0.125f;   // hd^-0.5
                if (diag && cc > r) val = -1e9f;
                Ss[r * SP + cc] = val;
            }
        }
        __syncthreads();

        // Online softmax: 4 lanes per row
        {
            int row = tid >> 2, part = tid & 3;
            int cbeg = part * 16;
            float mx = -3.0e38f;
            #pragma unroll
            for (int c = 0; c < 16; c++) mx = fmaxf(mx, Ss[row * SP + cbeg + c]);
            mx = fmaxf(mx, __shfl_xor_sync(0xffffffffu, mx, 1));
            mx = fmaxf(mx, __shfl_xor_sync(0xffffffffu, mx, 2));
            float mold = m_s[row];
            float mnew = fmaxf(mold, mx);
            float sum = 0.f;
            #pragma unroll
            for (int c = 0; c < 16; c++) {
                float p = __expf(Ss[row * SP + cbeg + c] - mnew);
                Ss[row * SP + cbeg + c] = p;
                sum += p;
            }
            sum += __shfl_xor_sync(0xffffffffu, sum, 1);
            sum += __shfl_xor_sync(0xffffffffu, sum, 2);
            if (part == 0) {
                float alpha = __expf(mold - mnew);
                al_s[row] = alpha;
                l_s[row]  = l_s[row] * alpha + sum;
                m_s[row]  = mnew;
            }
        }
        __syncthreads();

        // Rescale O, then O += P @ V
        float alph[4];
        #pragma unroll
        for (int i = 0; i < 4; i++) alph[i] = al_s[ty * 4 + i];
        #pragma unroll
        for (int i = 0; i < 4; i++)
            #pragma unroll
            for (int j = 0; j < 4; j++) o[i][j] *= alph[i];

        #pragma unroll 8
        for (int c = 0; c < BKT; c++) {
            float p0 = Ss[(ty * 4 + 0) * SP + c];
            float p1 = Ss[(ty * 4 + 1) * SP + c];
            float p2 = Ss[(ty * 4 + 2) * SP + c];
            float p3 = Ss[(ty * 4 + 3) * SP + c];
            float4 vf = *(const float4*)&Vs[c * HD + tx * 4];
            float va[4] = {vf.x, vf.y, vf.z, vf.w};
            #pragma unroll
            for (int j = 0; j < 4; j++) {
                o[0][j] = fmaf(p0, va[j], o[0][j]);
                o[1][j] = fmaf(p1, va[j], o[1][j]);
                o[2][j] = fmaf(p2, va[j], o[2][j]);
                o[3][j] = fmaf(p3, va[j], o[3][j]);
            }
        }
        __syncthreads();
    }

    // Epilogue: normalize by l, write to [B,T,C]
    const int b = bh / H_, h = bh - b * H_;
    #pragma unroll
    for (int i = 0; i < 4; i++) {
        int r = ty * 4 + i;
        float inv = 1.f / l_s[r];
        int t = q0 + r;
        float4 res;
        res.x = o[i][0] * inv; res.y = o[i][1] * inv;
        res.z = o[i][2] * inv; res.w = o[i][3] * inv;
        *(float4*)&out[((size_t)(b * T_ + t)) * C_ + h * HD + tx * 4] = res;
    }
}

// =============================================================================
extern "C" void kernel_launch(void* const* d_in, const int* in_sizes, int n_in,
                              void* d_out, int out_size)
{
    (void)in_sizes; (void)n_in; (void)out_size;
    const float* x  = (const float*)d_in[0];
    const float* wq = (const float*)d_in[1];
    const float* bq = (const float*)d_in[2];
    const float* wk = (const float*)d_in[3];
    const float* bk = (const float*)d_in[4];
    const float* wv = (const float*)d_in[5];
    const float* bv = (const float*)d_in[6];
    const float* wo = (const float*)d_in[7];
    const float* bo = (const float*)d_in[8];
    float* out = (float*)d_out;

    float *q, *k, *v, *att;
    cudaGetSymbolAddress((void**)&q,   g_q);
    cudaGetSymbolAddress((void**)&k,   g_k);
    cudaGetSymbolAddress((void**)&v,   g_v);
    cudaGetSymbolAddress((void**)&att, g_att);

    dim3 gblk(C_ / 128, M_ / 128);   // (8, 64)

    gemm_bias_kernel<1><<<gblk, 256>>>(x, wq, bq, q);
    gemm_bias_kernel<1><<<gblk, 256>>>(x, wk, bk, k);
    gemm_bias_kernel<1><<<gblk, 256>>>(x, wv, bv, v);

    cudaFuncSetAttribute(attn_kernel,
                         cudaFuncAttributeMaxDynamicSharedMemorySize,
                         SMEM_ATT_BYTES);
    attn_kernel<<<dim3(B_ * H_, T_ / BQ), 256, SMEM_ATT_BYTES>>>(q, k, v, att);

    gemm_bias_kernel<0><<<gblk, 256>>>(att, wo, bo, out);
}

// round 3
// speedup vs baseline: 1.5387x; 1.5387x over previous
#include <cuda_runtime.h>
#include <cuda_bf16.h>
#include <math.h>
#include <stdint.h>

// Problem constants
constexpr int B_  = 4;
constexpr int T_  = 2048;
constexpr int C_  = 1024;
constexpr int H_  = 16;
constexpr int HD  = 64;          // head dim
constexpr int M_  = B_ * T_;     // 8192 rows for projections

// -------------------- scratch (static device allocations) --------------------
__device__ float g_q[B_ * H_ * T_ * HD];    // [B,H,T,hd]
__device__ float g_k[B_ * H_ * T_ * HD];
__device__ float g_v[B_ * H_ * T_ * HD];
__device__ float g_att[B_ * T_ * C_];       // [B,T,C] attention output (pre-proj)

// bf16 split-precision operands
__device__ __nv_bfloat16 g_ahi[M_ * C_];    // activations hi (x, later att)
__device__ __nv_bfloat16 g_alo[M_ * C_];    // activations lo
__device__ __nv_bfloat16 g_whi[4 * C_ * C_];// weights hi (q,k,v,o)
__device__ __nv_bfloat16 g_wlo[4 * C_ * C_];// weights lo

// =============================================================================
// helpers: mma.sync / ldmatrix / cp.async (compute_103-portable)
// =============================================================================
__device__ __forceinline__ uint32_t smem_u32(const void* p) {
    uint32_t a;
    asm("{ .reg .u64 t; cvta.to.shared.u64 t, %1; cvt.u32.u64 %0, t; }"
        : "=r"(a) : "l"(p));
    return a;
}

__device__ __forceinline__ void ldsm_x4(uint32_t addr, uint32_t* r) {
    asm volatile("ldmatrix.sync.aligned.m8n8.x4.shared.b16 {%0,%1,%2,%3}, [%4];"
                 : "=r"(r[0]), "=r"(r[1]), "=r"(r[2]), "=r"(r[3]) : "r"(addr));
}

__device__ __forceinline__ void mma_bf16(float* d, const uint32_t* a, const uint32_t* b) {
    asm volatile(
        "mma.sync.aligned.m16n8k16.row.col.f32.bf16.bf16.f32 "
        "{%0,%1,%2,%3}, {%4,%5,%6,%7}, {%8,%9}, {%0,%1,%2,%3};"
        : "+f"(d[0]), "+f"(d[1]), "+f"(d[2]), "+f"(d[3])
        : "r"(a[0]), "r"(a[1]), "r"(a[2]), "r"(a[3]), "r"(b[0]), "r"(b[1]));
}

__device__ __forceinline__ void cp_async16(uint32_t dst, const void* src) {
    asm volatile("cp.async.cg.shared.global [%0], [%1], 16;"
                 :: "r"(dst), "l"(src));
}
#define CP_ASYNC_COMMIT() asm volatile("cp.async.commit_group;" ::: "memory")
#define CP_ASYNC_WAIT(n)  asm volatile("cp.async.wait_group %0;" :: "n"(n) : "memory")

// =============================================================================
// split: fp32 -> bf16 hi + bf16 lo residual
// =============================================================================
__global__ __launch_bounds__(256) void split_kernel(
    const float* __restrict__ in, __nv_bfloat16* __restrict__ hi,
    __nv_bfloat16* __restrict__ lo, int n)
{
    int i = (blockIdx.x * 256 + threadIdx.x) * 4;
    if (i >= n) return;
    float4 v = *(const float4*)(in + i);
    __nv_bfloat16 h0 = __float2bfloat16_rn(v.x);
    __nv_bfloat16 h1 = __float2bfloat16_rn(v.y);
    __nv_bfloat16 h2 = __float2bfloat16_rn(v.z);
    __nv_bfloat16 h3 = __float2bfloat16_rn(v.w);
    __nv_bfloat16 l0 = __float2bfloat16_rn(v.x - __bfloat162float(h0));
    __nv_bfloat16 l1 = __float2bfloat16_rn(v.y - __bfloat162float(h1));
    __nv_bfloat16 l2 = __float2bfloat16_rn(v.z - __bfloat162float(h2));
    __nv_bfloat16 l3 = __float2bfloat16_rn(v.w - __bfloat162float(h3));
    __nv_bfloat162 hp0; hp0.x = h0; hp0.y = h1;
    __nv_bfloat162 hp1; hp1.x = h2; hp1.y = h3;
    __nv_bfloat162 lp0; lp0.x = l0; lp0.y = l1;
    __nv_bfloat162 lp1; lp1.x = l2; lp1.y = l3;
    *(__nv_bfloat162*)(hi + i)     = hp0;
    *(__nv_bfloat162*)(hi + i + 2) = hp1;
    *(__nv_bfloat162*)(lo + i)     = lp0;
    *(__nv_bfloat162*)(lo + i + 2) = lp1;
}

// =============================================================================
// mma.sync GEMM: out = A[M,K] @ W[N,K]^T + bias, split-bf16 x3, fp32 accum.
// CTA 128x128, BK=32, 8 warps (4m x 2n), warp tile 32x64, 2-stage cp.async.
// OUT_MODE 0: row-major [M,N]; OUT_MODE 1: scatter to [B,H,T,hd].
// =============================================================================
constexpr int RS_G        = 40;                      // smem row stride (bf16) -> 80B
constexpr int TILE_BYTES  = 128 * RS_G * 2;          // 10240
constexpr int STAGE_BYTES = 4 * TILE_BYTES;          // Ahi,Alo,Whi,Wlo
constexpr int GEMM_SMEM   = 2 * STAGE_BYTES;         // 81920

__device__ __forceinline__ void load_tile_async(
    uint32_t dst, const __nv_bfloat16* __restrict__ src,
    int rowbase, int k0, int tid)
{
    #pragma unroll
    for (int it = 0; it < 2; it++) {
        int id   = tid + it * 256;       // 512 chunks of 16B
        int row  = id >> 2;
        int quad = id & 3;
        cp_async16(dst + (uint32_t)(row * (RS_G * 2) + quad * 16),
                   (const char*)src +
                   ((size_t)(rowbase + row) * C_ + (size_t)k0 + quad * 8) * 2);
    }
}

template <int OUT_MODE>
__global__ __launch_bounds__(256, 1) void gemm_tc(
    const __nv_bfloat16* __restrict__ Ahi, const __nv_bfloat16* __restrict__ Alo,
    const __nv_bfloat16* __restrict__ Whi, const __nv_bfloat16* __restrict__ Wlo,
    const float* __restrict__ bias, float* __restrict__ out)
{
    extern __shared__ __align__(16) char smem[];
    const uint32_t sbase = smem_u32(smem);
    const int tid  = threadIdx.x;
    const int lane = tid & 31;
    const int w    = tid >> 5;
    const int wm0  = (w & 3) * 32;      // warp m offset in tile
    const int wn0  = (w >> 2) * 64;     // warp n offset in tile
    const int bm   = blockIdx.y * 128;
    const int bn   = blockIdx.x * 128;
    constexpr int NC = C_ / 32;         // 32 k-chunks

    float acc[2][8][4];
    #pragma unroll
    for (int mi = 0; mi < 2; mi++)
        #pragma unroll
        for (int ni = 0; ni < 8; ni++)
            #pragma unroll
            for (int t = 0; t < 4; t++) acc[mi][ni][t] = 0.f;

    // prologue: stage 0
    {
        uint32_t st = sbase;
        load_tile_async(st + 0 * TILE_BYTES, Ahi, bm, 0, tid);
        load_tile_async(st + 1 * TILE_BYTES, Alo, bm, 0, tid);
        load_tile_async(st + 2 * TILE_BYTES, Whi, bn, 0, tid);
        load_tile_async(st + 3 * TILE_BYTES, Wlo, bn, 0, tid);
        CP_ASYNC_COMMIT();
    }

    for (int ck = 0; ck < NC; ck++) {
        if (ck + 1 < NC) {
            uint32_t st = sbase + (uint32_t)((ck + 1) & 1) * STAGE_BYTES;
            int k0 = (ck + 1) * 32;
            load_tile_async(st + 0 * TILE_BYTES, Ahi, bm, k0, tid);
            load_tile_async(st + 1 * TILE_BYTES, Alo, bm, k0, tid);
            load_tile_async(st + 2 * TILE_BYTES, Whi, bn, k0, tid);
            load_tile_async(st + 3 * TILE_BYTES, Wlo, bn, k0, tid);
            CP_ASYNC_COMMIT();
            CP_ASYNC_WAIT(1);
        } else {
            CP_ASYNC_WAIT(0);
        }
        __syncthreads();

        const uint32_t st  = sbase + (uint32_t)(ck & 1) * STAGE_BYTES;
        const uint32_t sAh = st + 0 * TILE_BYTES;
        const uint32_t sAl = st + 1 * TILE_BYTES;
        const uint32_t sWh = st + 2 * TILE_BYTES;
        const uint32_t sWl = st + 3 * TILE_BYTES;

        #pragma unroll
        for (int kk = 0; kk < 2; kk++) {
            const int kc = kk * 16;
            uint32_t ah[2][4], al[2][4], wh[8][2], wl[8][2];
            // A fragments: lane -> row = l&15, col half = (l>>4)*8
            #pragma unroll
            for (int mi = 0; mi < 2; mi++) {
                int r = wm0 + mi * 16 + (lane & 15);
                int c = kc + ((lane >> 4) << 3);
                uint32_t off = (uint32_t)(r * (RS_G * 2) + c * 2);
                ldsm_x4(sAh + off, ah[mi]);
                ldsm_x4(sAl + off, al[mi]);
            }
            // W fragments: x4 covers n-block pair (2 x n8, both k halves)
            #pragma unroll
            for (int p = 0; p < 4; p++) {
                int r = wn0 + p * 16 + (lane & 7) + ((lane >> 4) & 1) * 8;
                int c = kc + ((lane >> 3) & 1) * 8;
                uint32_t off = (uint32_t)(r * (RS_G * 2) + c * 2);
                uint32_t tmp[4];
                ldsm_x4(sWh + off, tmp);
                wh[2 * p][0] = tmp[0]; wh[2 * p][1] = tmp[1];
                wh[2 * p + 1][0] = tmp[2]; wh[2 * p + 1][1] = tmp[3];
                ldsm_x4(sWl + off, tmp);
                wl[2 * p][0] = tmp[0]; wl[2 * p][1] = tmp[1];
                wl[2 * p + 1][0] = tmp[2]; wl[2 * p + 1][1] = tmp[3];
            }
            // 3-term split: hi*hi, hi*lo, lo*hi (16 indep tiles between reuse)
            #pragma unroll
            for (int mi = 0; mi < 2; mi++)
                #pragma unroll
                for (int ni = 0; ni < 8; ni++)
                    mma_bf16(acc[mi][ni], ah[mi], wh[ni]);
            #pragma unroll
            for (int mi = 0; mi < 2; mi++)
                #pragma unroll
                for (int ni = 0; ni < 8; ni++)
                    mma_bf16(acc[mi][ni], ah[mi], wl[ni]);
            #pragma unroll
            for (int mi = 0; mi < 2; mi++)
                #pragma unroll
                for (int ni = 0; ni < 8; ni++)
                    mma_bf16(acc[mi][ni], al[mi], wh[ni]);
        }
        __syncthreads();
    }

    // Epilogue: bias + store. Thread t of mma tile: rows (t/4, t/4+8), cols (t%4)*2+{0,1}
    #pragma unroll
    for (int mi = 0; mi < 2; mi++) {
        #pragma unroll
        for (int ni = 0; ni < 8; ni++) {
            int row0 = bm + wm0 + mi * 16 + (lane >> 2);
            int col  = bn + wn0 + ni * 8 + (lane & 3) * 2;
            float b0 = bias[col], b1 = bias[col + 1];
            float2 v0, v1;
            v0.x = acc[mi][ni][0] + b0; v0.y = acc[mi][ni][1] + b1;
            v1.x = acc[mi][ni][2] + b0; v1.y = acc[mi][ni][3] + b1;
            if (OUT_MODE == 0) {
                *(float2*)&out[(size_t)row0 * C_ + col]       = v0;
                *(float2*)&out[(size_t)(row0 + 8) * C_ + col] = v1;
            } else {
                int h = col >> 6, d = col & 63;
                {
                    int b = row0 >> 11, t = row0 & 2047;
                    *(float2*)&out[(((size_t)(b * H_ + h) * T_ + t) * HD) + d] = v0;
                }
                {
                    int r1 = row0 + 8;
                    int b = r1 >> 11, t = r1 & 2047;
                    *(float2*)&out[(((size_t)(b * H_ + h) * T_ + t) * HD) + d] = v1;
                }
            }
        }
    }
}

// =============================================================================
// Flash attention (causal) — unchanged (known passing).
// =============================================================================
constexpr int BQ  = 64;
constexpr int BKT = 64;
constexpr int SP  = 68;
constexpr int SMEM_ATT_FLOATS =
    HD * BQ + HD * BKT + BKT * HD + BQ * SP + 3 * BQ;
constexpr int SMEM_ATT_BYTES = SMEM_ATT_FLOATS * 4;

__global__ __launch_bounds__(256) void attn_kernel(
    const float* __restrict__ Q, const float* __restrict__ K,
    const float* __restrict__ V, float* __restrict__ out)
{
    extern __shared__ __align__(16) float sm[];
    float* Qs  = sm;
    float* Ks  = Qs + HD * BQ;
    float* Vs  = Ks + HD * BKT;
    float* Ss  = Vs + BKT * HD;
    float* m_s = Ss + BQ * SP;
    float* l_s = m_s + BQ;
    float* al_s = l_s + BQ;

    const int tid = threadIdx.x;
    const int tx  = tid & 15;
    const int ty  = tid >> 4;
    const int bh  = blockIdx.x;
    const int qi  = blockIdx.y;
    const int q0  = qi * BQ;

    const float* Qb = Q + (size_t)bh * T_ * HD;
    const float* Kb = K + (size_t)bh * T_ * HD;
    const float* Vb = V + (size_t)bh * T_ * HD;

    #pragma unroll
    for (int it = 0; it < 4; it++) {
        int id = tid + it * 256;
        int r  = id & 63;
        int c4 = (id >> 6) * 4;
        float4 qv = *(const float4*)&Qb[(size_t)(q0 + r) * HD + c4];
        Qs[(c4 + 0) * BQ + r] = qv.x; Qs[(c4 + 1) * BQ + r] = qv.y;
        Qs[(c4 + 2) * BQ + r] = qv.z; Qs[(c4 + 3) * BQ + r] = qv.w;
    }
    if (tid < BQ) { m_s[tid] = -3.0e38f; l_s[tid] = 0.f; }

    float o[4][4];
    #pragma unroll
    for (int i = 0; i < 4; i++)
        #pragma unroll
        for (int j = 0; j < 4; j++) o[i][j] = 0.f;

    __syncthreads();

    for (int kt = 0; kt <= qi; kt++) {
        const int k0 = kt * BKT;
        #pragma unroll
        for (int it = 0; it < 4; it++) {
            int id = tid + it * 256;
            {
                int r  = id & 63;
                int c4 = (id >> 6) * 4;
                float4 kv = *(const float4*)&Kb[(size_t)(k0 + r) * HD + c4];
                Ks[(c4 + 0) * BKT + r] = kv.x; Ks[(c4 + 1) * BKT + r] = kv.y;
                Ks[(c4 + 2) * BKT + r] = kv.z; Ks[(c4 + 3) * BKT + r] = kv.w;
            }
            {
                int r  = id >> 4;
                int c4 = (id & 15) * 4;
                float4 vv = *(const float4*)&Vb[(size_t)(k0 + r) * HD + c4];
                *(float4*)&Vs[r * HD + c4] = vv;
            }
        }
        __syncthreads();

        float s[4][4];
        #pragma unroll
        for (int i = 0; i < 4; i++)
            #pragma unroll
            for (int j = 0; j < 4; j++) s[i][j] = 0.f;

        #pragma unroll 8
        for (int d = 0; d < HD; d++) {
            float4 qf = *(const float4*)&Qs[d * BQ + ty * 4];
            float4 kf = *(const float4*)&Ks[d * BKT + tx * 4];
            float qa[4] = {qf.x, qf.y, qf.z, qf.w};
            float ka[4] = {kf.x, kf.y, kf.z, kf.w};
            #pragma unroll
            for (int i = 0; i < 4; i++)
                #pragma unroll
                for (int j = 0; j < 4; j++)
                    s[i][j] = fmaf(qa[i], ka[j], s[i][j]);
        }

        const bool diag = (kt == qi);
        #pragma unroll
        for (int i = 0; i < 4; i++) {
            int r = ty * 4 + i;
            #pragma unroll
            for (int j = 0; j < 4; j++) {
                int cc = tx * 4 + j;
                float val = s[i][j] * 0.125f;
                if (diag && cc > r) val = -1e9f;
                Ss[r * SP + cc] = val;
            }
        }
        __syncthreads();

        {
            int row = tid >> 2, part = tid & 3;
            int cbeg = part * 16;
            float mx = -3.0e38f;
            #pragma unroll
            for (int c = 0; c < 16; c++) mx = fmaxf(mx, Ss[row * SP + cbeg + c]);
            mx = fmaxf(mx, __shfl_xor_sync(0xffffffffu, mx, 1));
            mx = fmaxf(mx, __shfl_xor_sync(0xffffffffu, mx, 2));
            float mold = m_s[row];
            float mnew = fmaxf(mold, mx);
            float sum = 0.f;
            #pragma unroll
            for (int c = 0; c < 16; c++) {
                float p = __expf(Ss[row * SP + cbeg + c] - mnew);
                Ss[row * SP + cbeg + c] = p;
                sum += p;
            }
            sum += __shfl_xor_sync(0xffffffffu, sum, 1);
            sum += __shfl_xor_sync(0xffffffffu, sum, 2);
            if (part == 0) {
                float alpha = __expf(mold - mnew);
                al_s[row] = alpha;
                l_s[row]  = l_s[row] * alpha + sum;
                m_s[row]  = mnew;
            }
        }
        __syncthreads();

        float alph[4];
        #pragma unroll
        for (int i = 0; i < 4; i++) alph[i] = al_s[ty * 4 + i];
        #pragma unroll
        for (int i = 0; i < 4; i++)
            #pragma unroll
            for (int j = 0; j < 4; j++) o[i][j] *= alph[i];

        #pragma unroll 8
        for (int c = 0; c < BKT; c++) {
            float p0 = Ss[(ty * 4 + 0) * SP + c];
            float p1 = Ss[(ty * 4 + 1) * SP + c];
            float p2 = Ss[(ty * 4 + 2) * SP + c];
            float p3 = Ss[(ty * 4 + 3) * SP + c];
            float4 vf = *(const float4*)&Vs[c * HD + tx * 4];
            float va[4] = {vf.x, vf.y, vf.z, vf.w};
            #pragma unroll
            for (int j = 0; j < 4; j++) {
                o[0][j] = fmaf(p0, va[j], o[0][j]);
                o[1][j] = fmaf(p1, va[j], o[1][j]);
                o[2][j] = fmaf(p2, va[j], o[2][j]);
                o[3][j] = fmaf(p3, va[j], o[3][j]);
            }
        }
        __syncthreads();
    }

    const int b = bh / H_, h = bh - b * H_;
    #pragma unroll
    for (int i = 0; i < 4; i++) {
        int r = ty * 4 + i;
        float inv = 1.f / l_s[r];
        int t = q0 + r;
        float4 res;
        res.x = o[i][0] * inv; res.y = o[i][1] * inv;
        res.z = o[i][2] * inv; res.w = o[i][3] * inv;
        *(float4*)&out[((size_t)(b * T_ + t)) * C_ + h * HD + tx * 4] = res;
    }
}

// =============================================================================
extern "C" void kernel_launch(void* const* d_in, const int* in_sizes, int n_in,
                              void* d_out, int out_size)
{
    (void)in_sizes; (void)n_in; (void)out_size;
    const float* x  = (const float*)d_in[0];
    const float* wq = (const float*)d_in[1];
    const float* bq = (const float*)d_in[2];
    const float* wk = (const float*)d_in[3];
    const float* bk = (const float*)d_in[4];
    const float* wv = (const float*)d_in[5];
    const float* bv = (const float*)d_in[6];
    const float* wo = (const float*)d_in[7];
    const float* bo = (const float*)d_in[8];
    float* out = (float*)d_out;

    float *q, *k, *v, *att;
    __nv_bfloat16 *ahi, *alo, *whi, *wlo;
    cudaGetSymbolAddress((void**)&q,   g_q);
    cudaGetSymbolAddress((void**)&k,   g_k);
    cudaGetSymbolAddress((void**)&v,   g_v);
    cudaGetSymbolAddress((void**)&att, g_att);
    cudaGetSymbolAddress((void**)&ahi, g_ahi);
    cudaGetSymbolAddress((void**)&alo, g_alo);
    cudaGetSymbolAddress((void**)&whi, g_whi);
    cudaGetSymbolAddress((void**)&wlo, g_wlo);

    const int nX = M_ * C_;
    const int nW = C_ * C_;

    // split activations + all 4 weights to bf16 hi/lo
    split_kernel<<<nX / 1024, 256>>>(x,  ahi, alo, nX);
    split_kernel<<<nW / 1024, 256>>>(wq, whi + 0 * nW, wlo + 0 * nW, nW);
    split_kernel<<<nW / 1024, 256>>>(wk, whi + 1 * nW, wlo + 1 * nW, nW);
    split_kernel<<<nW / 1024, 256>>>(wv, whi + 2 * nW, wlo + 2 * nW, nW);
    split_kernel<<<nW / 1024, 256>>>(wo, whi + 3 * nW, wlo + 3 * nW, nW);

    cudaFuncSetAttribute(gemm_tc<0>, cudaFuncAttributeMaxDynamicSharedMemorySize,
                         GEMM_SMEM);
    cudaFuncSetAttribute(gemm_tc<1>, cudaFuncAttributeMaxDynamicSharedMemorySize,
                         GEMM_SMEM);

    dim3 gblk(C_ / 128, M_ / 128);   // (8, 64)
    gemm_tc<1><<<gblk, 256, GEMM_SMEM>>>(ahi, alo, whi + 0 * nW, wlo + 0 * nW, bq, q);
    gemm_tc<1><<<gblk, 256, GEMM_SMEM>>>(ahi, alo, whi + 1 * nW, wlo + 1 * nW, bk, k);
    gemm_tc<1><<<gblk, 256, GEMM_SMEM>>>(ahi, alo, whi + 2 * nW, wlo + 2 * nW, bv, v);

    cudaFuncSetAttribute(attn_kernel, cudaFuncAttributeMaxDynamicSharedMemorySize,
                         SMEM_ATT_BYTES);
    attn_kernel<<<dim3(B_ * H_, T_ / BQ), 256, SMEM_ATT_BYTES>>>(q, k, v, att);

    // split attention output, then O-projection
    split_kernel<<<nX / 1024, 256>>>(att, ahi, alo, nX);
    gemm_tc<0><<<gblk, 256, GEMM_SMEM>>>(ahi, alo, whi + 3 * nW, wlo + 3 * nW, bo, out);
}

// round 4
// speedup vs baseline: 2.5577x; 1.6622x over previous
#include <cuda_runtime.h>
#include <cuda_bf16.h>
#include <math.h>
#include <stdint.h>

// Problem constants
constexpr int B_  = 4;
constexpr int T_  = 2048;
constexpr int C_  = 1024;
constexpr int H_  = 16;
constexpr int HD  = 64;
constexpr int M_  = B_ * T_;

// -------------------- scratch (static device allocations) --------------------
__device__ __nv_bfloat16 g_ahi[M_ * C_];     // activations hi (x, later attn-out)
__device__ __nv_bfloat16 g_alo[M_ * C_];
__device__ __nv_bfloat16 g_whi[4 * C_ * C_]; // weights hi (q,k,v,o)
__device__ __nv_bfloat16 g_wlo[4 * C_ * C_];
__device__ __nv_bfloat16 g_qhi[B_ * H_ * T_ * HD];  // [B,H,T,hd]
__device__ __nv_bfloat16 g_qlo[B_ * H_ * T_ * HD];
__device__ __nv_bfloat16 g_khi[B_ * H_ * T_ * HD];
__device__ __nv_bfloat16 g_klo[B_ * H_ * T_ * HD];
__device__ __nv_bfloat16 g_vthi[B_ * H_ * HD * T_]; // [B,H,hd,T] (transposed)
__device__ __nv_bfloat16 g_vtlo[B_ * H_ * HD * T_];

// =============================================================================
// helpers (compute_103-portable)
// =============================================================================
__device__ __forceinline__ uint32_t smem_u32(const void* p) {
    uint32_t a;
    asm("{ .reg .u64 t; cvta.to.shared.u64 t, %1; cvt.u32.u64 %0, t; }"
        : "=r"(a) : "l"(p));
    return a;
}
__device__ __forceinline__ void ldsm_x4(uint32_t addr, uint32_t* r) {
    asm volatile("ldmatrix.sync.aligned.m8n8.x4.shared.b16 {%0,%1,%2,%3}, [%4];"
                 : "=r"(r[0]), "=r"(r[1]), "=r"(r[2]), "=r"(r[3]) : "r"(addr));
}
__device__ __forceinline__ void mma_bf16(float* d, const uint32_t* a, const uint32_t* b) {
    asm volatile(
        "mma.sync.aligned.m16n8k16.row.col.f32.bf16.bf16.f32 "
        "{%0,%1,%2,%3}, {%4,%5,%6,%7}, {%8,%9}, {%0,%1,%2,%3};"
        : "+f"(d[0]), "+f"(d[1]), "+f"(d[2]), "+f"(d[3])
        : "r"(a[0]), "r"(a[1]), "r"(a[2]), "r"(a[3]), "r"(b[0]), "r"(b[1]));
}
__device__ __forceinline__ void cp_async16(uint32_t dst, const void* src) {
    asm volatile("cp.async.cg.shared.global [%0], [%1], 16;" :: "r"(dst), "l"(src));
}
#define CP_ASYNC_COMMIT() asm volatile("cp.async.commit_group;" ::: "memory")
#define CP_ASYNC_WAIT(n)  asm volatile("cp.async.wait_group %0;" :: "n"(n) : "memory")

__device__ __forceinline__ float ex2f(float x) {
    float y;
    asm("ex2.approx.ftz.f32 %0, %1;" : "=f"(y) : "f"(x));
    return y;
}
// pack (x,y) -> bf16x2 hi + bf16x2 lo residual
__device__ __forceinline__ void psplit(float x, float y, uint32_t& hi, uint32_t& lo) {
    __nv_bfloat162 h = __floats2bfloat162_rn(x, y);
    float rx = x - __bfloat162float(h.x);
    float ry = y - __bfloat162float(h.y);
    __nv_bfloat162 l = __floats2bfloat162_rn(rx, ry);
    hi = *(uint32_t*)&h;
    lo = *(uint32_t*)&l;
}

// =============================================================================
// split: fp32 -> bf16 hi + bf16 lo residual
// =============================================================================
__global__ __launch_bounds__(256) void split_kernel(
    const float* __restrict__ in, __nv_bfloat16* __restrict__ hi,
    __nv_bfloat16* __restrict__ lo, int n)
{
    int i = (blockIdx.x * 256 + threadIdx.x) * 4;
    if (i >= n) return;
    float4 v = *(const float4*)(in + i);
    uint32_t h0, l0, h1, l1;
    psplit(v.x, v.y, h0, l0);
    psplit(v.z, v.w, h1, l1);
    *(uint32_t*)(hi + i)     = h0;
    *(uint32_t*)(hi + i + 2) = h1;
    *(uint32_t*)(lo + i)     = l0;
    *(uint32_t*)(lo + i + 2) = l1;
}

// =============================================================================
// mma.sync GEMM: out = A[M,K] @ W[N,K]^T + bias, split-bf16 x3, fp32 accum.
// OUT_MODE 0: fp32 row-major [M,N]
// OUT_MODE 2: bf16 hi/lo scattered to [B,H,T,hd]
// OUT_MODE 3: bf16 hi/lo scattered TRANSPOSED to [B,H,hd,T]
// =============================================================================
constexpr int RS_G        = 40;
constexpr int TILE_BYTES  = 128 * RS_G * 2;
constexpr int STAGE_BYTES = 4 * TILE_BYTES;
constexpr int GEMM_SMEM   = 2 * STAGE_BYTES;

__device__ __forceinline__ void load_tile_async(
    uint32_t dst, const __nv_bfloat16* __restrict__ src,
    int rowbase, int k0, int tid)
{
    #pragma unroll
    for (int it = 0; it < 2; it++) {
        int id   = tid + it * 256;
        int row  = id >> 2;
        int quad = id & 3;
        cp_async16(dst + (uint32_t)(row * (RS_G * 2) + quad * 16),
                   (const char*)src +
                   ((size_t)(rowbase + row) * C_ + (size_t)k0 + quad * 8) * 2);
    }
}

template <int OUT_MODE>
__global__ __launch_bounds__(256, 1) void gemm_tc(
    const __nv_bfloat16* __restrict__ Ahi, const __nv_bfloat16* __restrict__ Alo,
    const __nv_bfloat16* __restrict__ Whi, const __nv_bfloat16* __restrict__ Wlo,
    const float* __restrict__ bias, float* __restrict__ out,
    __nv_bfloat16* __restrict__ ohi, __nv_bfloat16* __restrict__ olo)
{
    extern __shared__ __align__(16) char smem[];
    const uint32_t sbase = smem_u32(smem);
    const int tid  = threadIdx.x;
    const int lane = tid & 31;
    const int w    = tid >> 5;
    const int wm0  = (w & 3) * 32;
    const int wn0  = (w >> 2) * 64;
    const int bm   = blockIdx.y * 128;
    const int bn   = blockIdx.x * 128;
    constexpr int NC = C_ / 32;

    float acc[2][8][4];
    #pragma unroll
    for (int mi = 0; mi < 2; mi++)
        #pragma unroll
        for (int ni = 0; ni < 8; ni++)
            #pragma unroll
            for (int t = 0; t < 4; t++) acc[mi][ni][t] = 0.f;

    {
        uint32_t st = sbase;
        load_tile_async(st + 0 * TILE_BYTES, Ahi, bm, 0, tid);
        load_tile_async(st + 1 * TILE_BYTES, Alo, bm, 0, tid);
        load_tile_async(st + 2 * TILE_BYTES, Whi, bn, 0, tid);
        load_tile_async(st + 3 * TILE_BYTES, Wlo, bn, 0, tid);
        CP_ASYNC_COMMIT();
    }

    for (int ck = 0; ck < NC; ck++) {
        if (ck + 1 < NC) {
            uint32_t st = sbase + (uint32_t)((ck + 1) & 1) * STAGE_BYTES;
            int k0 = (ck + 1) * 32;
            load_tile_async(st + 0 * TILE_BYTES, Ahi, bm, k0, tid);
            load_tile_async(st + 1 * TILE_BYTES, Alo, bm, k0, tid);
            load_tile_async(st + 2 * TILE_BYTES, Whi, bn, k0, tid);
            load_tile_async(st + 3 * TILE_BYTES, Wlo, bn, k0, tid);
            CP_ASYNC_COMMIT();
            CP_ASYNC_WAIT(1);
        } else {
            CP_ASYNC_WAIT(0);
        }
        __syncthreads();

        const uint32_t st  = sbase + (uint32_t)(ck & 1) * STAGE_BYTES;
        const uint32_t sAh = st + 0 * TILE_BYTES;
        const uint32_t sAl = st + 1 * TILE_BYTES;
        const uint32_t sWh = st + 2 * TILE_BYTES;
        const uint32_t sWl = st + 3 * TILE_BYTES;

        #pragma unroll
        for (int kk = 0; kk < 2; kk++) {
            const int kc = kk * 16;
            uint32_t ah[2][4], al[2][4], wh[8][2], wl[8][2];
            #pragma unroll
            for (int mi = 0; mi < 2; mi++) {
                int r = wm0 + mi * 16 + (lane & 15);
                int c = kc + ((lane >> 4) << 3);
                uint32_t off = (uint32_t)(r * (RS_G * 2) + c * 2);
                ldsm_x4(sAh + off, ah[mi]);
                ldsm_x4(sAl + off, al[mi]);
            }
            #pragma unroll
            for (int p = 0; p < 4; p++) {
                int r = wn0 + p * 16 + (lane & 7) + ((lane >> 4) & 1) * 8;
                int c = kc + ((lane >> 3) & 1) * 8;
                uint32_t off = (uint32_t)(r * (RS_G * 2) + c * 2);
                uint32_t tmp[4];
                ldsm_x4(sWh + off, tmp);
                wh[2 * p][0] = tmp[0]; wh[2 * p][1] = tmp[1];
                wh[2 * p + 1][0] = tmp[2]; wh[2 * p + 1][1] = tmp[3];
                ldsm_x4(sWl + off, tmp);
                wl[2 * p][0] = tmp[0]; wl[2 * p][1] = tmp[1];
                wl[2 * p + 1][0] = tmp[2]; wl[2 * p + 1][1] = tmp[3];
            }
            #pragma unroll
            for (int mi = 0; mi < 2; mi++)
                #pragma unroll
                for (int ni = 0; ni < 8; ni++)
                    mma_bf16(acc[mi][ni], ah[mi], wh[ni]);
            #pragma unroll
            for (int mi = 0; mi < 2; mi++)
                #pragma unroll
                for (int ni = 0; ni < 8; ni++)
                    mma_bf16(acc[mi][ni], ah[mi], wl[ni]);
            #pragma unroll
            for (int mi = 0; mi < 2; mi++)
                #pragma unroll
                for (int ni = 0; ni < 8; ni++)
                    mma_bf16(acc[mi][ni], al[mi], wh[ni]);
        }
        __syncthreads();
    }

    // Epilogue
    #pragma unroll
    for (int mi = 0; mi < 2; mi++) {
        #pragma unroll
        for (int ni = 0; ni < 8; ni++) {
            int row0 = bm + wm0 + mi * 16 + (lane >> 2);
            int col  = bn + wn0 + ni * 8 + (lane & 3) * 2;
            float b0 = bias[col], b1 = bias[col + 1];
            float v00 = acc[mi][ni][0] + b0, v01 = acc[mi][ni][1] + b1;
            float v10 = acc[mi][ni][2] + b0, v11 = acc[mi][ni][3] + b1;
            if (OUT_MODE == 0) {
                float2 a; a.x = v00; a.y = v01;
                float2 c; c.x = v10; c.y = v11;
                *(float2*)&out[(size_t)row0 * C_ + col]       = a;
                *(float2*)&out[(size_t)(row0 + 8) * C_ + col] = c;
            } else if (OUT_MODE == 2) {
                int h = col >> 6, d = col & 63;
                uint32_t hh, ll;
                {
                    int b = row0 >> 11, t = row0 & 2047;
                    size_t o = ((size_t)((b * H_ + h) * T_ + t)) * HD + d;
                    psplit(v00, v01, hh, ll);
                    *(uint32_t*)(ohi + o) = hh; *(uint32_t*)(olo + o) = ll;
                }
                {
                    int r1 = row0 + 8;
                    int b = r1 >> 11, t = r1 & 2047;
                    size_t o = ((size_t)((b * H_ + h) * T_ + t)) * HD + d;
                    psplit(v10, v11, hh, ll);
                    *(uint32_t*)(ohi + o) = hh; *(uint32_t*)(olo + o) = ll;
                }
            } else { // OUT_MODE 3: transposed [B,H,hd,T]
                int h = col >> 6, d = col & 63;
                int b = row0 >> 11, t = row0 & 2047;
                int bhh = b * H_ + h;
                size_t base0 = ((size_t)(bhh * HD + d)) * T_;
                size_t base1 = ((size_t)(bhh * HD + d + 1)) * T_;
                __nv_bfloat16 h00 = __float2bfloat16_rn(v00);
                __nv_bfloat16 h01 = __float2bfloat16_rn(v01);
                __nv_bfloat16 h10 = __float2bfloat16_rn(v10);
                __nv_bfloat16 h11 = __float2bfloat16_rn(v11);
                ohi[base0 + t]     = h00;
                ohi[base1 + t]     = h01;
                ohi[base0 + t + 8] = h10;
                ohi[base1 + t + 8] = h11;
                olo[base0 + t]     = __float2bfloat16_rn(v00 - __bfloat162float(h00));
                olo[base1 + t]     = __float2bfloat16_rn(v01 - __bfloat162float(h01));
                olo[base0 + t + 8] = __float2bfloat16_rn(v10 - __bfloat162float(h10));
                olo[base1 + t + 8] = __float2bfloat16_rn(v11 - __bfloat162float(h11));
            }
        }
    }
}

// =============================================================================
// Tensor-core flash attention (causal).
// CTA: (bh, qi) with BQ=128 q rows, 8 warps x 16 rows. kt tiles of 64.
// S = Q@K^T and O += P@V via m16n8k16 bf16, 3-term split. Softmax in registers.
// Output: split-bf16 into [B,T,C] hi/lo buffers.
// =============================================================================
constexpr int ARS       = 72;                       // smem row stride (bf16): 144B
constexpr int QS_BYTES  = 128 * ARS * 2;            // 18432
constexpr int KVT_BYTES = 64 * ARS * 2;             // 9216
constexpr int ATT_SMEM  = 2 * QS_BYTES + 2 * 4 * KVT_BYTES;  // 110592

__device__ __forceinline__ void att_load_kv(
    uint32_t sKh, uint32_t sKl, uint32_t sVh, uint32_t sVl,
    const __nv_bfloat16* __restrict__ khi, const __nv_bfloat16* __restrict__ klo,
    const __nv_bfloat16* __restrict__ vthi, const __nv_bfloat16* __restrict__ vtlo,
    int bh, int k0, int tid)
{
    #pragma unroll
    for (int it = 0; it < 2; it++) {
        int id  = tid + it * 256;
        int row = id >> 3;
        int ch  = id & 7;
        uint32_t so = (uint32_t)(row * (ARS * 2) + ch * 16);
        size_t goK = ((size_t)(bh * T_ + k0 + row) * HD + ch * 8) * 2;
        cp_async16(sKh + so, (const char*)khi + goK);
        cp_async16(sKl + so, (const char*)klo + goK);
        size_t goV = ((size_t)(bh * HD + row) * T_ + k0 + ch * 8) * 2;
        cp_async16(sVh + so, (const char*)vthi + goV);
        cp_async16(sVl + so, (const char*)vtlo + goV);
    }
}

__global__ __launch_bounds__(256, 1) void attn_tc(
    const __nv_bfloat16* __restrict__ qhi, const __nv_bfloat16* __restrict__ qlo,
    const __nv_bfloat16* __restrict__ khi, const __nv_bfloat16* __restrict__ klo,
    const __nv_bfloat16* __restrict__ vthi, const __nv_bfloat16* __restrict__ vtlo,
    __nv_bfloat16* __restrict__ out_hi, __nv_bfloat16* __restrict__ out_lo)
{
    extern __shared__ __align__(16) char smem[];
    const uint32_t sb  = smem_u32(smem);
    const uint32_t sQh = sb, sQl = sb + QS_BYTES;
    const int tid  = threadIdx.x;
    const int lane = tid & 31;
    const int w    = tid >> 5;
    const int bh   = blockIdx.x;
    const int qi   = blockIdx.y;
    const int q0   = qi * 128;
    const int ktmax = 2 * qi + 1;
    const float SC = 0.18033688011112042f;   // hd^-0.5 * log2(e)

    // prologue loads: Q tiles + KV tile 0 (one cp.async group)
    #pragma unroll
    for (int it = 0; it < 4; it++) {
        int id  = tid + it * 256;
        int row = id >> 3;
        int ch  = id & 7;
        uint32_t so = (uint32_t)(row * (ARS * 2) + ch * 16);
        size_t go = ((size_t)(bh * T_ + q0 + row) * HD + ch * 8) * 2;
        cp_async16(sQh + so, (const char*)qhi + go);
        cp_async16(sQl + so, (const char*)qlo + go);
    }
    {
        uint32_t skv = sb + 2 * QS_BYTES;
        att_load_kv(skv, skv + KVT_BYTES, skv + 2 * KVT_BYTES, skv + 3 * KVT_BYTES,
                    khi, klo, vthi, vtlo, bh, 0, tid);
    }
    CP_ASYNC_COMMIT();

    float o[8][4];
    #pragma unroll
    for (int n = 0; n < 8; n++)
        #pragma unroll
        for (int t = 0; t < 4; t++) o[n][t] = 0.f;
    float m0 = -1e30f, m1 = -1e30f, l0 = 0.f, l1 = 0.f;
    uint32_t qfh[4][4], qfl[4][4];

    const int rlo_base = q0 + w * 16 + (lane >> 2);

    for (int kt = 0; kt <= ktmax; kt++) {
        const int s = kt & 1;
        __syncthreads();   // previous compute done before overwriting other stage
        if (kt + 1 <= ktmax) {
            uint32_t skv = sb + 2 * QS_BYTES + (uint32_t)(s ^ 1) * 4 * KVT_BYTES;
            att_load_kv(skv, skv + KVT_BYTES, skv + 2 * KVT_BYTES, skv + 3 * KVT_BYTES,
                        khi, klo, vthi, vtlo, bh, (kt + 1) * 64, tid);
            CP_ASYNC_COMMIT();
            CP_ASYNC_WAIT(1);
        } else {
            CP_ASYNC_WAIT(0);
        }
        __syncthreads();

        if (kt == 0) {
            // preload Q fragments (held in registers for whole loop)
            #pragma unroll
            for (int kc = 0; kc < 4; kc++) {
                uint32_t off = (uint32_t)((w * 16 + (lane & 15)) * (ARS * 2)
                                          + kc * 32 + ((lane >> 4) << 4));
                ldsm_x4(sQh + off, qfh[kc]);
                ldsm_x4(sQl + off, qfl[kc]);
            }
        }

        // skip fully-masked warp tiles (all still hit the syncthreads above)
        if (kt * 64 > q0 + w * 16 + 15) continue;

        const uint32_t skv = sb + 2 * QS_BYTES + (uint32_t)s * 4 * KVT_BYTES;
        const uint32_t sKh = skv, sKl = skv + KVT_BYTES;
        const uint32_t sVh = skv + 2 * KVT_BYTES, sVl = skv + 3 * KVT_BYTES;

        // ---- S = Q @ K^T (3-term split) ----
        float sv[8][4];
        #pragma unroll
        for (int n = 0; n < 8; n++)
            #pragma unroll
            for (int t = 0; t < 4; t++) sv[n][t] = 0.f;

        #pragma unroll
        for (int kc = 0; kc < 4; kc++) {
            uint32_t kh[8][2], kl[8][2];
            #pragma unroll
            for (int p = 0; p < 4; p++) {
                uint32_t off = (uint32_t)((p * 16 + (lane & 7) + ((lane >> 4) & 1) * 8)
                                          * (ARS * 2) + kc * 32 + ((lane >> 3) & 1) * 16);
                uint32_t tmp[4];
                ldsm_x4(sKh + off, tmp);
                kh[2 * p][0] = tmp[0]; kh[2 * p][1] = tmp[1];
                kh[2 * p + 1][0] = tmp[2]; kh[2 * p + 1][1] = tmp[3];
                ldsm_x4(sKl + off, tmp);
                kl[2 * p][0] = tmp[0]; kl[2 * p][1] = tmp[1];
                kl[2 * p + 1][0] = tmp[2]; kl[2 * p + 1][1] = tmp[3];
            }
            #pragma unroll
            for (int n = 0; n < 8; n++) mma_bf16(sv[n], qfh[kc], kh[n]);
            #pragma unroll
            for (int n = 0; n < 8; n++) mma_bf16(sv[n], qfh[kc], kl[n]);
            #pragma unroll
            for (int n = 0; n < 8; n++) mma_bf16(sv[n], qfl[kc], kh[n]);
        }

        // ---- scale + causal mask + online softmax (registers only) ----
        const int rlo = rlo_base;
        const int rhi = rlo + 8;
        const bool needmask = (kt * 64 + 63 > q0 + w * 16);
        float mx0 = m0, mx1 = m1;
        #pragma unroll
        for (int n = 0; n < 8; n++) {
            int j = kt * 64 + n * 8 + (lane & 3) * 2;
            sv[n][0] *= SC; sv[n][1] *= SC; sv[n][2] *= SC; sv[n][3] *= SC;
            if (needmask) {
                if (j     > rlo) sv[n][0] = -1e30f;
                if (j + 1 > rlo) sv[n][1] = -1e30f;
                if (j     > rhi) sv[n][2] = -1e30f;
                if (j + 1 > rhi) sv[n][3] = -1e30f;
            }
            mx0 = fmaxf(mx0, fmaxf(sv[n][0], sv[n][1]));
            mx1 = fmaxf(mx1, fmaxf(sv[n][2], sv[n][3]));
        }
        mx0 = fmaxf(mx0, __shfl_xor_sync(0xffffffffu, mx0, 1));
        mx0 = fmaxf(mx0, __shfl_xor_sync(0xffffffffu, mx0, 2));
        mx1 = fmaxf(mx1, __shfl_xor_sync(0xffffffffu, mx1, 1));
        mx1 = fmaxf(mx1, __shfl_xor_sync(0xffffffffu, mx1, 2));
        const float a0 = ex2f(m0 - mx0);
        const float a1 = ex2f(m1 - mx1);
        m0 = mx0; m1 = mx1;

        float sum0 = 0.f, sum1 = 0.f;
        #pragma unroll
        for (int n = 0; n < 8; n++) {
            sv[n][0] = ex2f(sv[n][0] - mx0);
            sv[n][1] = ex2f(sv[n][1] - mx0);
            sv[n][2] = ex2f(sv[n][2] - mx1);
            sv[n][3] = ex2f(sv[n][3] - mx1);
            sum0 += sv[n][0] + sv[n][1];
            sum1 += sv[n][2] + sv[n][3];
        }
        l0 = l0 * a0 + sum0;     // lane-partial; reduced at epilogue
        l1 = l1 * a1 + sum1;
        #pragma unroll
        for (int n = 0; n < 8; n++) {
            o[n][0] *= a0; o[n][1] *= a0; o[n][2] *= a1; o[n][3] *= a1;
        }

        // ---- pack P accumulators into A-fragments (hi + lo) ----
        uint32_t ph[4][4], pl[4][4];
        #pragma unroll
        for (int kc = 0; kc < 4; kc++) {
            psplit(sv[2 * kc][0],     sv[2 * kc][1],     ph[kc][0], pl[kc][0]);
            psplit(sv[2 * kc][2],     sv[2 * kc][3],     ph[kc][1], pl[kc][1]);
            psplit(sv[2 * kc + 1][0], sv[2 * kc + 1][1], ph[kc][2], pl[kc][2]);
            psplit(sv[2 * kc + 1][2], sv[2 * kc + 1][3], ph[kc][3], pl[kc][3]);
        }

        // ---- O += P @ V (3-term split), V in [d][t] smem ----
        #pragma unroll
        for (int kc = 0; kc < 4; kc++) {
            uint32_t vh[8][2], vl[8][2];
            #pragma unroll
            for (int p = 0; p < 4; p++) {
                uint32_t off = (uint32_t)((p * 16 + (lane & 7) + ((lane >> 4) & 1) * 8)
                                          * (ARS * 2) + kc * 32 + ((lane >> 3) & 1) * 16);
                uint32_t tmp[4];
                ldsm_x4(sVh + off, tmp);
                vh[2 * p][0] = tmp[0]; vh[2 * p][1] = tmp[1];
                vh[2 * p + 1][0] = tmp[2]; vh[2 * p + 1][1] = tmp[3];
                ldsm_x4(sVl + off, tmp);
                vl[2 * p][0] = tmp[0]; vl[2 * p][1] = tmp[1];
                vl[2 * p + 1][0] = tmp[2]; vl[2 * p + 1][1] = tmp[3];
            }
            #pragma unroll
            for (int n = 0; n < 8; n++) mma_bf16(o[n], ph[kc], vh[n]);
            #pragma unroll
            for (int n = 0; n < 8; n++) mma_bf16(o[n], ph[kc], vl[n]);
            #pragma unroll
            for (int n = 0; n < 8; n++) mma_bf16(o[n], pl[kc], vh[n]);
        }
    }

    // ---- epilogue: finish l reduce, normalize, split-store to [B,T,C] ----
    l0 += __shfl_xor_sync(0xffffffffu, l0, 1);
    l0 += __shfl_xor_sync(0xffffffffu, l0, 2);
    l1 += __shfl_xor_sync(0xffffffffu, l1, 1);
    l1 += __shfl_xor_sync(0xffffffffu, l1, 2);
    const float inv0 = 1.f / l0;
    const float inv1 = 1.f / l1;

    const int b = bh >> 4, h = bh & 15;
    const int t0 = q0 + w * 16 + (lane >> 2);
    const int t1 = t0 + 8;
    #pragma unroll
    for (int n = 0; n < 8; n++) {
        int d = n * 8 + (lane & 3) * 2;
        uint32_t hh, ll;
        size_t o0 = ((size_t)(b * T_ + t0)) * C_ + h * HD + d;
        psplit(o[n][0] * inv0, o[n][1] * inv0, hh, ll);
        *(uint32_t*)(out_hi + o0) = hh;
        *(uint32_t*)(out_lo + o0) = ll;
        size_t o1 = ((size_t)(b * T_ + t1)) * C_ + h * HD + d;
        psplit(o[n][2] * inv1, o[n][3] * inv1, hh, ll);
        *(uint32_t*)(out_hi + o1) = hh;
        *(uint32_t*)(out_lo + o1) = ll;
    }
}

// =============================================================================
extern "C" void kernel_launch(void* const* d_in, const int* in_sizes, int n_in,
                              void* d_out, int out_size)
{
    (void)in_sizes; (void)n_in; (void)out_size;
    const float* x  = (const float*)d_in[0];
    const float* wq = (const float*)d_in[1];
    const float* bq = (const float*)d_in[2];
    const float* wk = (const float*)d_in[3];
    const float* bk = (const float*)d_in[4];
    const float* wv = (const float*)d_in[5];
    const float* bv = (const float*)d_in[6];
    const float* wo = (const float*)d_in[7];
    const float* bo = (const float*)d_in[8];
    float* out = (float*)d_out;

    __nv_bfloat16 *ahi, *alo, *whi, *wlo;
    __nv_bfloat16 *qhi, *qlo, *khi, *klo, *vthi, *vtlo;
    cudaGetSymbolAddress((void**)&ahi,  g_ahi);
    cudaGetSymbolAddress((void**)&alo,  g_alo);
    cudaGetSymbolAddress((void**)&whi,  g_whi);
    cudaGetSymbolAddress((void**)&wlo,  g_wlo);
    cudaGetSymbolAddress((void**)&qhi,  g_qhi);
    cudaGetSymbolAddress((void**)&qlo,  g_qlo);
    cudaGetSymbolAddress((void**)&khi,  g_khi);
    cudaGetSymbolAddress((void**)&klo,  g_klo);
    cudaGetSymbolAddress((void**)&vthi, g_vthi);
    cudaGetSymbolAddress((void**)&vtlo, g_vtlo);

    const int nX = M_ * C_;
    const int nW = C_ * C_;

    split_kernel<<<nX / 1024, 256>>>(x,  ahi, alo, nX);
    split_kernel<<<nW / 1024, 256>>>(wq, whi + 0 * nW, wlo + 0 * nW, nW);
    split_kernel<<<nW / 1024, 256>>>(wk, whi + 1 * nW, wlo + 1 * nW, nW);
    split_kernel<<<nW / 1024, 256>>>(wv, whi + 2 * nW, wlo + 2 * nW, nW);
    split_kernel<<<nW / 1024, 256>>>(wo, whi + 3 * nW, wlo + 3 * nW, nW);

    cudaFuncSetAttribute(gemm_tc<0>, cudaFuncAttributeMaxDynamicSharedMemorySize, GEMM_SMEM);
    cudaFuncSetAttribute(gemm_tc<2>, cudaFuncAttributeMaxDynamicSharedMemorySize, GEMM_SMEM);
    cudaFuncSetAttribute(gemm_tc<3>, cudaFuncAttributeMaxDynamicSharedMemorySize, GEMM_SMEM);
    cudaFuncSetAttribute(attn_tc,    cudaFuncAttributeMaxDynamicSharedMemorySize, ATT_SMEM);

    dim3 gblk(C_ / 128, M_ / 128);   // (8, 64)
    gemm_tc<2><<<gblk, 256, GEMM_SMEM>>>(ahi, alo, whi + 0 * nW, wlo + 0 * nW, bq,
                                         nullptr, qhi, qlo);
    gemm_tc<2><<<gblk, 256, GEMM_SMEM>>>(ahi, alo, whi + 1 * nW, wlo + 1 * nW, bk,
                                         nullptr, khi, klo);
    gemm_tc<3><<<gblk, 256, GEMM_SMEM>>>(ahi, alo, whi + 2 * nW, wlo + 2 * nW, bv,
                                         nullptr, vthi, vtlo);

    // attention overwrites ahi/alo with split attention output
    attn_tc<<<dim3(B_ * H_, T_ / 128), 256, ATT_SMEM>>>(qhi, qlo, khi, klo,
                                                        vthi, vtlo, ahi, alo);

    gemm_tc<0><<<gblk, 256, GEMM_SMEM>>>(ahi, alo, whi + 3 * nW, wlo + 3 * nW, bo,
                                         out, nullptr, nullptr);
}

// round 7
// speedup vs baseline: 3.1266x; 1.2224x over previous
#include <cuda_runtime.h>
#include <cuda_bf16.h>
#include <math.h>
#include <stdint.h>

// Problem constants
constexpr int B_  = 4;
constexpr int T_  = 2048;
constexpr int C_  = 1024;
constexpr int H_  = 16;
constexpr int HD  = 64;
constexpr int M_  = B_ * T_;

// -------------------- scratch (static device allocations) --------------------
__device__ __nv_bfloat16 g_ahi[M_ * C_];     // activations hi (x, later attn-out)
__device__ __nv_bfloat16 g_alo[M_ * C_];
__device__ __nv_bfloat16 g_whi[4 * C_ * C_]; // weights hi (q,k,v,o)
__device__ __nv_bfloat16 g_wlo[4 * C_ * C_];
__device__ __nv_bfloat16 g_qhi[B_ * H_ * T_ * HD];  // [B,H,T,hd]
__device__ __nv_bfloat16 g_qlo[B_ * H_ * T_ * HD];
__device__ __nv_bfloat16 g_khi[B_ * H_ * T_ * HD];
__device__ __nv_bfloat16 g_klo[B_ * H_ * T_ * HD];
__device__ __nv_bfloat16 g_vthi[B_ * H_ * HD * T_]; // [B,H,hd,T] (transposed)
__device__ __nv_bfloat16 g_vtlo[B_ * H_ * HD * T_];

// =============================================================================
// helpers (compute_103-portable)
// =============================================================================
__device__ __forceinline__ uint32_t smem_u32(const void* p) {
    uint32_t a;
    asm("{ .reg .u64 t; cvta.to.shared.u64 t, %1; cvt.u32.u64 %0, t; }"
        : "=r"(a) : "l"(p));
    return a;
}
__device__ __forceinline__ void ldsm_x4(uint32_t addr, uint32_t* r) {
    asm volatile("ldmatrix.sync.aligned.m8n8.x4.shared.b16 {%0,%1,%2,%3}, [%4];"
                 : "=r"(r[0]), "=r"(r[1]), "=r"(r[2]), "=r"(r[3]) : "r"(addr));
}
__device__ __forceinline__ void mma_bf16(float* d, const uint32_t* a, const uint32_t* b) {
    asm volatile(
        "mma.sync.aligned.m16n8k16.row.col.f32.bf16.bf16.f32 "
        "{%0,%1,%2,%3}, {%4,%5,%6,%7}, {%8,%9}, {%0,%1,%2,%3};"
        : "+f"(d[0]), "+f"(d[1]), "+f"(d[2]), "+f"(d[3])
        : "r"(a[0]), "r"(a[1]), "r"(a[2]), "r"(a[3]), "r"(b[0]), "r"(b[1]));
}
__device__ __forceinline__ void cp_async16(uint32_t dst, const void* src) {
    asm volatile("cp.async.cg.shared.global [%0], [%1], 16;" :: "r"(dst), "l"(src));
}
#define CP_ASYNC_COMMIT() asm volatile("cp.async.commit_group;" ::: "memory")
#define CP_ASYNC_WAIT(n)  asm volatile("cp.async.wait_group %0;" :: "n"(n) : "memory")

__device__ __forceinline__ float ex2f(float x) {
    float y;
    asm("ex2.approx.ftz.f32 %0, %1;" : "=f"(y) : "f"(x));
    return y;
}
// pack (x,y) -> bf16x2 hi + bf16x2 lo residual
__device__ __forceinline__ void psplit(float x, float y, uint32_t& hi, uint32_t& lo) {
    __nv_bfloat162 h = __floats2bfloat162_rn(x, y);
    float rx = x - __bfloat162float(h.x);
    float ry = y - __bfloat162float(h.y);
    __nv_bfloat162 l = __floats2bfloat162_rn(rx, ry);
    hi = *(uint32_t*)&h;
    lo = *(uint32_t*)&l;
}

// =============================================================================
// split: fp32 -> bf16 hi + bf16 lo residual
// =============================================================================
__global__ __launch_bounds__(256) void split_kernel(
    const float* __restrict__ in, __nv_bfloat16* __restrict__ hi,
    __nv_bfloat16* __restrict__ lo, int n)
{
    int i = (blockIdx.x * 256 + threadIdx.x) * 4;
    if (i >= n) return;
    float4 v = *(const float4*)(in + i);
    uint32_t h0, l0, h1, l1;
    psplit(v.x, v.y, h0, l0);
    psplit(v.z, v.w, h1, l1);
    *(uint32_t*)(hi + i)     = h0;
    *(uint32_t*)(hi + i + 2) = h1;
    *(uint32_t*)(lo + i)     = l0;
    *(uint32_t*)(lo + i + 2) = l1;
}

// =============================================================================
// GEMM mainloop (shared): acc = A[M,K] @ W[N,K]^T, split-bf16 x3, fp32 accum.
// CTA 128x128, BK=32, 8 warps (4m x 2n), 2-stage cp.async, 2 CTAs/SM.
// =============================================================================
constexpr int RS_G        = 40;
constexpr int TILE_BYTES  = 128 * RS_G * 2;          // 10240
constexpr int STAGE_BYTES = 4 * TILE_BYTES;          // 40960
constexpr int GEMM_SMEM   = 2 * STAGE_BYTES;         // 81920

__device__ __forceinline__ void load_tile_async(
    uint32_t dst, const __nv_bfloat16* __restrict__ src,
    int rowbase, int k0, int tid)
{
    #pragma unroll
    for (int it = 0; it < 2; it++) {
        int id   = tid + it * 256;
        int row  = id >> 2;
        int quad = id & 3;
        cp_async16(dst + (uint32_t)(row * (RS_G * 2) + quad * 16),
                   (const char*)src +
                   ((size_t)(rowbase + row) * C_ + (size_t)k0 + quad * 8) * 2);
    }
}

__device__ __forceinline__ void gemm_mainloop(
    uint32_t sbase,
    const __nv_bfloat16* __restrict__ Ahi, const __nv_bfloat16* __restrict__ Alo,
    const __nv_bfloat16* __restrict__ Whi, const __nv_bfloat16* __restrict__ Wlo,
    int bm, int bn, int tid, float acc[2][8][4])
{
    const int lane = tid & 31;
    const int w    = tid >> 5;
    const int wm0  = (w & 3) * 32;
    const int wn0  = (w >> 2) * 64;
    constexpr int NC = C_ / 32;

    {
        uint32_t st = sbase;
        load_tile_async(st + 0 * TILE_BYTES, Ahi, bm, 0, tid);
        load_tile_async(st + 1 * TILE_BYTES, Alo, bm, 0, tid);
        load_tile_async(st + 2 * TILE_BYTES, Whi, bn, 0, tid);
        load_tile_async(st + 3 * TILE_BYTES, Wlo, bn, 0, tid);
        CP_ASYNC_COMMIT();
    }

    for (int ck = 0; ck < NC; ck++) {
        if (ck + 1 < NC) {
            uint32_t st = sbase + (uint32_t)((ck + 1) & 1) * STAGE_BYTES;
            int k0 = (ck + 1) * 32;
            load_tile_async(st + 0 * TILE_BYTES, Ahi, bm, k0, tid);
            load_tile_async(st + 1 * TILE_BYTES, Alo, bm, k0, tid);
            load_tile_async(st + 2 * TILE_BYTES, Whi, bn, k0, tid);
            load_tile_async(st + 3 * TILE_BYTES, Wlo, bn, k0, tid);
            CP_ASYNC_COMMIT();
            CP_ASYNC_WAIT(1);
        } else {
            CP_ASYNC_WAIT(0);
        }
        __syncthreads();

        const uint32_t st  = sbase + (uint32_t)(ck & 1) * STAGE_BYTES;
        const uint32_t sAh = st + 0 * TILE_BYTES;
        const uint32_t sAl = st + 1 * TILE_BYTES;
        const uint32_t sWh = st + 2 * TILE_BYTES;
        const uint32_t sWl = st + 3 * TILE_BYTES;

        #pragma unroll
        for (int kk = 0; kk < 2; kk++) {
            const int kc = kk * 16;
            uint32_t ah[2][4], al[2][4];
            #pragma unroll
            for (int mi = 0; mi < 2; mi++) {
                int r = wm0 + mi * 16 + (lane & 15);
                int c = kc + ((lane >> 4) << 3);
                uint32_t off = (uint32_t)(r * (RS_G * 2) + c * 2);
                ldsm_x4(sAh + off, ah[mi]);
                ldsm_x4(sAl + off, al[mi]);
            }
            // One W-fragment pair (2 n-tiles) live at a time -> low reg pressure
            #pragma unroll
            for (int p = 0; p < 4; p++) {
                int r = wn0 + p * 16 + (lane & 7) + ((lane >> 4) & 1) * 8;
                int c = kc + ((lane >> 3) & 1) * 8;
                uint32_t off = (uint32_t)(r * (RS_G * 2) + c * 2);
                uint32_t wh[4], wl[4];
                ldsm_x4(sWh + off, wh);
                ldsm_x4(sWl + off, wl);
                #pragma unroll
                for (int mi = 0; mi < 2; mi++) {
                    mma_bf16(acc[mi][2 * p],     ah[mi], wh + 0);
                    mma_bf16(acc[mi][2 * p + 1], ah[mi], wh + 2);
                    mma_bf16(acc[mi][2 * p],     ah[mi], wl + 0);
                    mma_bf16(acc[mi][2 * p + 1], ah[mi], wl + 2);
                    mma_bf16(acc[mi][2 * p],     al[mi], wh + 0);
                    mma_bf16(acc[mi][2 * p + 1], al[mi], wh + 2);
                }
            }
        }
        __syncthreads();
    }
}

// ---------- fused QKV projection: z selects {q,k,v}; v stored transposed ----
__global__ __launch_bounds__(256, 2) void gemm_qkv(
    const __nv_bfloat16* __restrict__ Ahi, const __nv_bfloat16* __restrict__ Alo,
    const __nv_bfloat16* __restrict__ Wh,  const __nv_bfloat16* __restrict__ Wl,
    const float* __restrict__ b0, const float* __restrict__ b1,
    const float* __restrict__ b2,
    __nv_bfloat16* __restrict__ qh, __nv_bfloat16* __restrict__ ql,
    __nv_bfloat16* __restrict__ kh, __nv_bfloat16* __restrict__ kl,
    __nv_bfloat16* __restrict__ vh, __nv_bfloat16* __restrict__ vl)
{
    extern __shared__ __align__(16) char smem[];
    const uint32_t sbase = smem_u32(smem);
    const int tid = threadIdx.x;
    const int bm  = blockIdx.y * 128;
    const int bn  = blockIdx.x * 128;
    const int z   = blockIdx.z;
    const int nW  = C_ * C_;

    const float* bias = (z == 0) ? b0 : (z == 1) ? b1 : b2;
    __nv_bfloat16* ohi = (z == 0) ? qh : (z == 1) ? kh : vh;
    __nv_bfloat16* olo = (z == 0) ? ql : (z == 1) ? kl : vl;

    float acc[2][8][4];
    #pragma unroll
    for (int mi = 0; mi < 2; mi++)
        #pragma unroll
        for (int ni = 0; ni < 8; ni++)
            #pragma unroll
            for (int t = 0; t < 4; t++) acc[mi][ni][t] = 0.f;

    gemm_mainloop(sbase, Ahi, Alo, Wh + (size_t)z * nW, Wl + (size_t)z * nW,
                  bm, bn, tid, acc);

    const int lane = tid & 31;
    const int w    = tid >> 5;
    const int wm0  = (w & 3) * 32;
    const int wn0  = (w >> 2) * 64;

    #pragma unroll
    for (int mi = 0; mi < 2; mi++) {
        #pragma unroll
        for (int ni = 0; ni < 8; ni++) {
            int row0 = bm + wm0 + mi * 16 + (lane >> 2);
            int col  = bn + wn0 + ni * 8 + (lane & 3) * 2;
            float bb0 = bias[col], bb1 = bias[col + 1];
            float v00 = acc[mi][ni][0] + bb0, v01 = acc[mi][ni][1] + bb1;
            float v10 = acc[mi][ni][2] + bb0, v11 = acc[mi][ni][3] + bb1;
            int h = col >> 6, d = col & 63;
            if (z < 2) {   // [B,H,T,hd]
                uint32_t hh, ll;
                {
                    int b = row0 >> 11, t = row0 & 2047;
                    size_t o = ((size_t)((b * H_ + h) * T_ + t)) * HD + d;
                    psplit(v00, v01, hh, ll);
                    *(uint32_t*)(ohi + o) = hh; *(uint32_t*)(olo + o) = ll;
                }
                {
                    int r1 = row0 + 8;
                    int b = r1 >> 11, t = r1 & 2047;
                    size_t o = ((size_t)((b * H_ + h) * T_ + t)) * HD + d;
                    psplit(v10, v11, hh, ll);
                    *(uint32_t*)(ohi + o) = hh; *(uint32_t*)(olo + o) = ll;
                }
            } else {       // V transposed [B,H,hd,T]
                int b = row0 >> 11, t = row0 & 2047;
                int bhh = b * H_ + h;
                size_t base0 = ((size_t)(bhh * HD + d)) * T_;
                size_t base1 = ((size_t)(bhh * HD + d + 1)) * T_;
                __nv_bfloat16 h00 = __float2bfloat16_rn(v00);
                __nv_bfloat16 h01 = __float2bfloat16_rn(v01);
                __nv_bfloat16 h10 = __float2bfloat16_rn(v10);
                __nv_bfloat16 h11 = __float2bfloat16_rn(v11);
                ohi[base0 + t]     = h00;
                ohi[base1 + t]     = h01;
                ohi[base0 + t + 8] = h10;
                ohi[base1 + t + 8] = h11;
                olo[base0 + t]     = __float2bfloat16_rn(v00 - __bfloat162float(h00));
                olo[base1 + t]     = __float2bfloat16_rn(v01 - __bfloat162float(h01));
                olo[base0 + t + 8] = __float2bfloat16_rn(v10 - __bfloat162float(h10));
                olo[base1 + t + 8] = __float2bfloat16_rn(v11 - __bfloat162float(h11));
            }
        }
    }
}

// ---------- O-projection: fp32 row-major output ----------
__global__ __launch_bounds__(256, 2) void gemm_out(
    const __nv_bfloat16* __restrict__ Ahi, const __nv_bfloat16* __restrict__ Alo,
    const __nv_bfloat16* __restrict__ Whi, const __nv_bfloat16* __restrict__ Wlo,
    const float* __restrict__ bias, float* __restrict__ out)
{
    extern __shared__ __align__(16) char smem[];
    const uint32_t sbase = smem_u32(smem);
    const int tid = threadIdx.x;
    const int bm  = blockIdx.y * 128;
    const int bn  = blockIdx.x * 128;

    float acc[2][8][4];
    #pragma unroll
    for (int mi = 0; mi < 2; mi++)
        #pragma unroll
        for (int ni = 0; ni < 8; ni++)
            #pragma unroll
            for (int t = 0; t < 4; t++) acc[mi][ni][t] = 0.f;

    gemm_mainloop(sbase, Ahi, Alo, Whi, Wlo, bm, bn, tid, acc);

    const int lane = tid & 31;
    const int w    = tid >> 5;
    const int wm0  = (w & 3) * 32;
    const int wn0  = (w >> 2) * 64;

    #pragma unroll
    for (int mi = 0; mi < 2; mi++) {
        #pragma unroll
        for (int ni = 0; ni < 8; ni++) {
            int row0 = bm + wm0 + mi * 16 + (lane >> 2);
            int col  = bn + wn0 + ni * 8 + (lane & 3) * 2;
            float b0 = bias[col], b1 = bias[col + 1];
            float2 a; a.x = acc[mi][ni][0] + b0; a.y = acc[mi][ni][1] + b1;
            float2 c; c.x = acc[mi][ni][2] + b0; c.y = acc[mi][ni][3] + b1;
            *(float2*)&out[(size_t)row0 * C_ + col]       = a;
            *(float2*)&out[(size_t)(row0 + 8) * C_ + col] = c;
        }
    }
}

// =============================================================================
// Tensor-core flash attention (causal). Longest q-tiles scheduled first.
// =============================================================================
constexpr int ARS       = 72;
constexpr int QS_BYTES  = 128 * ARS * 2;
constexpr int KVT_BYTES = 64 * ARS * 2;
constexpr int ATT_SMEM  = 2 * QS_BYTES + 2 * 4 * KVT_BYTES;

__device__ __forceinline__ void att_load_kv(
    uint32_t sKh, uint32_t sKl, uint32_t sVh, uint32_t sVl,
    const __nv_bfloat16* __restrict__ khi, const __nv_bfloat16* __restrict__ klo,
    const __nv_bfloat16* __restrict__ vthi, const __nv_bfloat16* __restrict__ vtlo,
    int bh, int k0, int tid)
{
    #pragma unroll
    for (int it = 0; it < 2; it++) {
        int id  = tid + it * 256;
        int row = id >> 3;
        int ch  = id & 7;
        uint32_t so = (uint32_t)(row * (ARS * 2) + ch * 16);
        size_t goK = ((size_t)(bh * T_ + k0 + row) * HD + ch * 8) * 2;
        cp_async16(sKh + so, (const char*)khi + goK);
        cp_async16(sKl + so, (const char*)klo + goK);
        size_t goV = ((size_t)(bh * HD + row) * T_ + k0 + ch * 8) * 2;
        cp_async16(sVh + so, (const char*)vthi + goV);
        cp_async16(sVl + so, (const char*)vtlo + goV);
    }
}

__global__ __launch_bounds__(256, 1) void attn_tc(
    const __nv_bfloat16* __restrict__ qhi, const __nv_bfloat16* __restrict__ qlo,
    const __nv_bfloat16* __restrict__ khi, const __nv_bfloat16* __restrict__ klo,
    const __nv_bfloat16* __restrict__ vthi, const __nv_bfloat16* __restrict__ vtlo,
    __nv_bfloat16* __restrict__ out_hi, __nv_bfloat16* __restrict__ out_lo)
{
    extern __shared__ __align__(16) char smem[];
    const uint32_t sb  = smem_u32(smem);
    const uint32_t sQh = sb, sQl = sb + QS_BYTES;
    const int tid  = threadIdx.x;
    const int lane = tid & 31;
    const int w    = tid >> 5;
    const int bh   = blockIdx.x;
    const int qi   = (int)gridDim.y - 1 - (int)blockIdx.y;  // longest first
    const int q0   = qi * 128;
    const int ktmax = 2 * qi + 1;
    const float SC = 0.18033688011112042f;   // hd^-0.5 * log2(e)

    #pragma unroll
    for (int it = 0; it < 4; it++) {
        int id  = tid + it * 256;
        int row = id >> 3;
        int ch  = id & 7;
        uint32_t so = (uint32_t)(row * (ARS * 2) + ch * 16);
        size_t go = ((size_t)(bh * T_ + q0 + row) * HD + ch * 8) * 2;
        cp_async16(sQh + so, (const char*)qhi + go);
        cp_async16(sQl + so, (const char*)qlo + go);
    }
    {
        uint32_t skv = sb + 2 * QS_BYTES;
        att_load_kv(skv, skv + KVT_BYTES, skv + 2 * KVT_BYTES, skv + 3 * KVT_BYTES,
                    khi, klo, vthi, vtlo, bh, 0, tid);
    }
    CP_ASYNC_COMMIT();

    float o[8][4];
    #pragma unroll
    for (int n = 0; n < 8; n++)
        #pragma unroll
        for (int t = 0; t < 4; t++) o[n][t] = 0.f;
    float m0 = -1e30f, m1 = -1e30f, l0 = 0.f, l1 = 0.f;
    uint32_t qfh[4][4], qfl[4][4];

    const int rlo_base = q0 + w * 16 + (lane >> 2);

    for (int kt = 0; kt <= ktmax; kt++) {
        const int s = kt & 1;
        __syncthreads();
        if (kt + 1 <= ktmax) {
            uint32_t skv = sb + 2 * QS_BYTES + (uint32_t)(s ^ 1) * 4 * KVT_BYTES;
            att_load_kv(skv, skv + KVT_BYTES, skv + 2 * KVT_BYTES, skv + 3 * KVT_BYTES,
                        khi, klo, vthi, vtlo, bh, (kt + 1) * 64, tid);
            CP_ASYNC_COMMIT();
            CP_ASYNC_WAIT(1);
        } else {
            CP_ASYNC_WAIT(0);
        }
        __syncthreads();

        if (kt == 0) {
            #pragma unroll
            for (int kc = 0; kc < 4; kc++) {
                uint32_t off = (uint32_t)((w * 16 + (lane & 15)) * (ARS * 2)
                                          + kc * 32 + ((lane >> 4) << 4));
                ldsm_x4(sQh + off, qfh[kc]);
                ldsm_x4(sQl + off, qfl[kc]);
            }
        }

        if (kt * 64 > q0 + w * 16 + 15) continue;

        const uint32_t skv = sb + 2 * QS_BYTES + (uint32_t)s * 4 * KVT_BYTES;
        const uint32_t sKh = skv, sKl = skv + KVT_BYTES;
        const uint32_t sVh = skv + 2 * KVT_BYTES, sVl = skv + 3 * KVT_BYTES;

        float sv[8][4];
        #pragma unroll
        for (int n = 0; n < 8; n++)
            #pragma unroll
            for (int t = 0; t < 4; t++) sv[n][t] = 0.f;

        #pragma unroll
        for (int kc = 0; kc < 4; kc++) {
            uint32_t kh[8][2], kl[8][2];
            #pragma unroll
            for (int p = 0; p < 4; p++) {
                uint32_t off = (uint32_t)((p * 16 + (lane & 7) + ((lane >> 4) & 1) * 8)
                                          * (ARS * 2) + kc * 32 + ((lane >> 3) & 1) * 16);
                uint32_t tmp[4];
                ldsm_x4(sKh + off, tmp);
                kh[2 * p][0] = tmp[0]; kh[2 * p][1] = tmp[1];
                kh[2 * p + 1][0] = tmp[2]; kh[2 * p + 1][1] = tmp[3];
                ldsm_x4(sKl + off, tmp);
                kl[2 * p][0] = tmp[0]; kl[2 * p][1] = tmp[1];
                kl[2 * p + 1][0] = tmp[2]; kl[2 * p + 1][1] = tmp[3];
            }
            #pragma unroll
            for (int n = 0; n < 8; n++) mma_bf16(sv[n], qfh[kc], kh[n]);
            #pragma unroll
            for (int n = 0; n < 8; n++) mma_bf16(sv[n], qfh[kc], kl[n]);
            #pragma unroll
            for (int n = 0; n < 8; n++) mma_bf16(sv[n], qfl[kc], kh[n]);
        }

        const int rlo = rlo_base;
        const int rhi = rlo + 8;
        const bool needmask = (kt * 64 + 63 > q0 + w * 16);
        float mx0 = m0, mx1 = m1;
        #pragma unroll
        for (int n = 0; n < 8; n++) {
            int j = kt * 64 + n * 8 + (lane & 3) * 2;
            sv[n][0] *= SC; sv[n][1] *= SC; sv[n][2] *= SC; sv[n][3] *= SC;
            if (needmask) {
                if (j     > rlo) sv[n][0] = -1e30f;
                if (j + 1 > rlo) sv[n][1] = -1e30f;
                if (j     > rhi) sv[n][2] = -1e30f;
                if (j + 1 > rhi) sv[n][3] = -1e30f;
            }
            mx0 = fmaxf(mx0, fmaxf(sv[n][0], sv[n][1]));
            mx1 = fmaxf(mx1, fmaxf(sv[n][2], sv[n][3]));
        }
        mx0 = fmaxf(mx0, __shfl_xor_sync(0xffffffffu, mx0, 1));
        mx0 = fmaxf(mx0, __shfl_xor_sync(0xffffffffu, mx0, 2));
        mx1 = fmaxf(mx1, __shfl_xor_sync(0xffffffffu, mx1, 1));
        mx1 = fmaxf(mx1, __shfl_xor_sync(0xffffffffu, mx1, 2));
        const float a0 = ex2f(m0 - mx0);
        const float a1 = ex2f(m1 - mx1);
        m0 = mx0; m1 = mx1;

        float sum0 = 0.f, sum1 = 0.f;
        #pragma unroll
        for (int n = 0; n < 8; n++) {
            sv[n][0] = ex2f(sv[n][0] - mx0);
            sv[n][1] = ex2f(sv[n][1] - mx0);
            sv[n][2] = ex2f(sv[n][2] - mx1);
            sv[n][3] = ex2f(sv[n][3] - mx1);
            sum0 += sv[n][0] + sv[n][1];
            sum1 += sv[n][2] + sv[n][3];
        }
        l0 = l0 * a0 + sum0;
        l1 = l1 * a1 + sum1;
        #pragma unroll
        for (int n = 0; n < 8; n++) {
            o[n][0] *= a0; o[n][1] *= a0; o[n][2] *= a1; o[n][3] *= a1;
        }

        uint32_t ph[4][4], pl[4][4];
        #pragma unroll
        for (int kc = 0; kc < 4; kc++) {
            psplit(sv[2 * kc][0],     sv[2 * kc][1],     ph[kc][0], pl[kc][0]);
            psplit(sv[2 * kc][2],     sv[2 * kc][3],     ph[kc][1], pl[kc][1]);
            psplit(sv[2 * kc + 1][0], sv[2 * kc + 1][1], ph[kc][2], pl[kc][2]);
            psplit(sv[2 * kc + 1][2], sv[2 * kc + 1][3], ph[kc][3], pl[kc][3]);
        }

        #pragma unroll
        for (int kc = 0; kc < 4; kc++) {
            uint32_t vh[8][2], vl[8][2];
            #pragma unroll
            for (int p = 0; p < 4; p++) {
                uint32_t off = (uint32_t)((p * 16 + (lane & 7) + ((lane >> 4) & 1) * 8)
                                          * (ARS * 2) + kc * 32 + ((lane >> 3) & 1) * 16);
                uint32_t tmp[4];
                ldsm_x4(sVh + off, tmp);
                vh[2 * p][0] = tmp[0]; vh[2 * p][1] = tmp[1];
                vh[2 * p + 1][0] = tmp[2]; vh[2 * p + 1][1] = tmp[3];
                ldsm_x4(sVl + off, tmp);
                vl[2 * p][0] = tmp[0]; vl[2 * p][1] = tmp[1];
                vl[2 * p + 1][0] = tmp[2]; vl[2 * p + 1][1] = tmp[3];
            }
            #pragma unroll
            for (int n = 0; n < 8; n++) mma_bf16(o[n], ph[kc], vh[n]);
            #pragma unroll
            for (int n = 0; n < 8; n++) mma_bf16(o[n], ph[kc], vl[n]);
            #pragma unroll
            for (int n = 0; n < 8; n++) mma_bf16(o[n], pl[kc], vh[n]);
        }
    }

    l0 += __shfl_xor_sync(0xffffffffu, l0, 1);
    l0 += __shfl_xor_sync(0xffffffffu, l0, 2);
    l1 += __shfl_xor_sync(0xffffffffu, l1, 1);
    l1 += __shfl_xor_sync(0xffffffffu, l1, 2);
    const float inv0 = 1.f / l0;
    const float inv1 = 1.f / l1;

    const int b = bh >> 4, h = bh & 15;
    const int t0 = q0 + w * 16 + (lane >> 2);
    const int t1 = t0 + 8;
    #pragma unroll
    for (int n = 0; n < 8; n++) {
        int d = n * 8 + (lane & 3) * 2;
        uint32_t hh, ll;
        size_t o0 = ((size_t)(b * T_ + t0)) * C_ + h * HD + d;
        psplit(o[n][0] * inv0, o[n][1] * inv0, hh, ll);
        *(uint32_t*)(out_hi + o0) = hh;
        *(uint32_t*)(out_lo + o0) = ll;
        size_t o1 = ((size_t)(b * T_ + t1)) * C_ + h * HD + d;
        psplit(o[n][2] * inv1, o[n][3] * inv1, hh, ll);
        *(uint32_t*)(out_hi + o1) = hh;
        *(uint32_t*)(out_lo + o1) = ll;
    }
}

// =============================================================================
extern "C" void kernel_launch(void* const* d_in, const int* in_sizes, int n_in,
                              void* d_out, int out_size)
{
    (void)in_sizes; (void)n_in; (void)out_size;
    const float* x  = (const float*)d_in[0];
    const float* wq = (const float*)d_in[1];
    const float* bq = (const float*)d_in[2];
    const float* wk = (const float*)d_in[3];
    const float* bk = (const float*)d_in[4];
    const float* wv = (const float*)d_in[5];
    const float* bv = (const float*)d_in[6];
    const float* wo = (const float*)d_in[7];
    const float* bo = (const float*)d_in[8];
    float* out = (float*)d_out;

    __nv_bfloat16 *ahi, *alo, *whi, *wlo;
    __nv_bfloat16 *qhi, *qlo, *khi, *klo, *vthi, *vtlo;
    cudaGetSymbolAddress((void**)&ahi,  g_ahi);
    cudaGetSymbolAddress((void**)&alo,  g_alo);
    cudaGetSymbolAddress((void**)&whi,  g_whi);
    cudaGetSymbolAddress((void**)&wlo,  g_wlo);
    cudaGetSymbolAddress((void**)&qhi,  g_qhi);
    cudaGetSymbolAddress((void**)&qlo,  g_qlo);
    cudaGetSymbolAddress((void**)&khi,  g_khi);
    cudaGetSymbolAddress((void**)&klo,  g_klo);
    cudaGetSymbolAddress((void**)&vthi, g_vthi);
    cudaGetSymbolAddress((void**)&vtlo, g_vtlo);

    const int nX = M_ * C_;
    const int nW = C_ * C_;

    split_kernel<<<nX / 1024, 256>>>(x,  ahi, alo, nX);
    split_kernel<<<nW / 1024, 256>>>(wq, whi + 0 * nW, wlo + 0 * nW, nW);
    split_kernel<<<nW / 1024, 256>>>(wk, whi + 1 * nW, wlo + 1 * nW, nW);
    split_kernel<<<nW / 1024, 256>>>(wv, whi + 2 * nW, wlo + 2 * nW, nW);
    split_kernel<<<nW / 1024, 256>>>(wo, whi + 3 * nW, wlo + 3 * nW, nW);

    cudaFuncSetAttribute(gemm_qkv, cudaFuncAttributeMaxDynamicSharedMemorySize, GEMM_SMEM);
    cudaFuncSetAttribute(gemm_out, cudaFuncAttributeMaxDynamicSharedMemorySize, GEMM_SMEM);
    cudaFuncSetAttribute(attn_tc,  cudaFuncAttributeMaxDynamicSharedMemorySize, ATT_SMEM);

    // fused QKV projections (z = 0,1,2)
    gemm_qkv<<<dim3(C_ / 128, M_ / 128, 3), 256, GEMM_SMEM>>>(
        ahi, alo, whi, wlo, bq, bk, bv, qhi, qlo, khi, klo, vthi, vtlo);

    // attention overwrites ahi/alo with split attention output
    attn_tc<<<dim3(B_ * H_, T_ / 128), 256, ATT_SMEM>>>(qhi, qlo, khi, klo,
                                                        vthi, vtlo, ahi, alo);

    gemm_out<<<dim3(C_ / 128, M_ / 128), 256, GEMM_SMEM>>>(
        ahi, alo, whi + 3 * nW, wlo + 3 * nW, bo, out);
}

// round 8
// speedup vs baseline: 3.2128x; 1.0276x over previous
#include <cuda_runtime.h>
#include <cuda_bf16.h>
#include <math.h>
#include <stdint.h>

// Problem constants
constexpr int B_  = 4;
constexpr int T_  = 2048;
constexpr int C_  = 1024;
constexpr int H_  = 16;
constexpr int HD  = 64;
constexpr int M_  = B_ * T_;

// -------------------- scratch (static device allocations) --------------------
__device__ __nv_bfloat16 g_ahi[M_ * C_];     // activations hi (x, later attn-out)
__device__ __nv_bfloat16 g_alo[M_ * C_];
__device__ __nv_bfloat16 g_whi[4 * C_ * C_]; // weights hi (q,k,v,o)
__device__ __nv_bfloat16 g_wlo[4 * C_ * C_];
__device__ __nv_bfloat16 g_qhi[B_ * H_ * T_ * HD];  // [B,H,T,hd]
__device__ __nv_bfloat16 g_qlo[B_ * H_ * T_ * HD];
__device__ __nv_bfloat16 g_khi[B_ * H_ * T_ * HD];
__device__ __nv_bfloat16 g_klo[B_ * H_ * T_ * HD];
__device__ __nv_bfloat16 g_vthi[B_ * H_ * HD * T_]; // [B,H,hd,T] (transposed)
__device__ __nv_bfloat16 g_vtlo[B_ * H_ * HD * T_];

// =============================================================================
// helpers (compute_103-portable)
// =============================================================================
__device__ __forceinline__ uint32_t smem_u32(const void* p) {
    uint32_t a;
    asm("{ .reg .u64 t; cvta.to.shared.u64 t, %1; cvt.u32.u64 %0, t; }"
        : "=r"(a) : "l"(p));
    return a;
}
__device__ __forceinline__ void ldsm_x4(uint32_t addr, uint32_t* r) {
    asm volatile("ldmatrix.sync.aligned.m8n8.x4.shared.b16 {%0,%1,%2,%3}, [%4];"
                 : "=r"(r[0]), "=r"(r[1]), "=r"(r[2]), "=r"(r[3]) : "r"(addr));
}
__device__ __forceinline__ void mma_bf16(float* d, const uint32_t* a, const uint32_t* b) {
    asm volatile(
        "mma.sync.aligned.m16n8k16.row.col.f32.bf16.bf16.f32 "
        "{%0,%1,%2,%3}, {%4,%5,%6,%7}, {%8,%9}, {%0,%1,%2,%3};"
        : "+f"(d[0]), "+f"(d[1]), "+f"(d[2]), "+f"(d[3])
        : "r"(a[0]), "r"(a[1]), "r"(a[2]), "r"(a[3]), "r"(b[0]), "r"(b[1]));
}
__device__ __forceinline__ void cp_async16(uint32_t dst, const void* src) {
    asm volatile("cp.async.cg.shared.global [%0], [%1], 16;" :: "r"(dst), "l"(src));
}
#define CP_ASYNC_COMMIT() asm volatile("cp.async.commit_group;" ::: "memory")
#define CP_ASYNC_WAIT(n)  asm volatile("cp.async.wait_group %0;" :: "n"(n) : "memory")

__device__ __forceinline__ float ex2f(float x) {
    float y;
    asm("ex2.approx.ftz.f32 %0, %1;" : "=f"(y) : "f"(x));
    return y;
}
// pack (x,y) -> bf16x2 hi + bf16x2 lo residual
__device__ __forceinline__ void psplit(float x, float y, uint32_t& hi, uint32_t& lo) {
    __nv_bfloat162 h = __floats2bfloat162_rn(x, y);
    float rx = x - __bfloat162float(h.x);
    float ry = y - __bfloat162float(h.y);
    __nv_bfloat162 l = __floats2bfloat162_rn(rx, ry);
    hi = *(uint32_t*)&h;
    lo = *(uint32_t*)&l;
}

// =============================================================================
// fused split: fp32 -> bf16 hi + lo for x and all 4 weight matrices, 1 launch
// blocks [0, 8192): x ; blocks [8192, 12288): weights (1024 blocks each)
// =============================================================================
__global__ __launch_bounds__(256) void split_all(
    const float* __restrict__ x,
    const float* __restrict__ wq, const float* __restrict__ wk,
    const float* __restrict__ wv, const float* __restrict__ wo,
    __nv_bfloat16* __restrict__ ahi, __nv_bfloat16* __restrict__ alo,
    __nv_bfloat16* __restrict__ whi, __nv_bfloat16* __restrict__ wlo)
{
    const int nW = C_ * C_;
    int blk = blockIdx.x;
    const float* src;
    __nv_bfloat16 *hi, *lo;
    int base;
    if (blk < 8192) {
        src = x; hi = ahi; lo = alo; base = blk;
    } else {
        int r = blk - 8192;
        int ws = r >> 10;          // 0..3
        base = r & 1023;
        src = (ws == 0) ? wq : (ws == 1) ? wk : (ws == 2) ? wv : wo;
        hi = whi + (size_t)ws * nW;
        lo = wlo + (size_t)ws * nW;
    }
    int i = (base * 256 + threadIdx.x) * 4;
    float4 v = *(const float4*)(src + i);
    uint32_t h0, l0, h1, l1;
    psplit(v.x, v.y, h0, l0);
    psplit(v.z, v.w, h1, l1);
    *(uint32_t*)(hi + i)     = h0;
    *(uint32_t*)(hi + i + 2) = h1;
    *(uint32_t*)(lo + i)     = l0;
    *(uint32_t*)(lo + i + 2) = l1;
}

// =============================================================================
// GEMM mainloop (shared): acc = A[M,K] @ W[N,K]^T, split-bf16 x3, fp32 accum.
// CTA 128x128, BK=32, 8 warps (4m x 2n), 2-stage cp.async, 2 CTAs/SM.
// Single __syncthreads per chunk: wait -> sync -> issue next -> compute.
// =============================================================================
constexpr int RS_G        = 40;
constexpr int TILE_BYTES  = 128 * RS_G * 2;          // 10240
constexpr int STAGE_BYTES = 4 * TILE_BYTES;          // 40960
constexpr int GEMM_SMEM   = 2 * STAGE_BYTES;         // 81920

__device__ __forceinline__ void load_tile_async(
    uint32_t dst, const __nv_bfloat16* __restrict__ src,
    int rowbase, int k0, int tid)
{
    #pragma unroll
    for (int it = 0; it < 2; it++) {
        int id   = tid + it * 256;
        int row  = id >> 2;
        int quad = id & 3;
        cp_async16(dst + (uint32_t)(row * (RS_G * 2) + quad * 16),
                   (const char*)src +
                   ((size_t)(rowbase + row) * C_ + (size_t)k0 + quad * 8) * 2);
    }
}

__device__ __forceinline__ void gemm_mainloop(
    uint32_t sbase,
    const __nv_bfloat16* __restrict__ Ahi, const __nv_bfloat16* __restrict__ Alo,
    const __nv_bfloat16* __restrict__ Whi, const __nv_bfloat16* __restrict__ Wlo,
    int bm, int bn, int tid, float acc[2][8][4])
{
    const int lane = tid & 31;
    const int w    = tid >> 5;
    const int wm0  = (w & 3) * 32;
    const int wn0  = (w >> 2) * 64;
    constexpr int NC = C_ / 32;

    {
        uint32_t st = sbase;
        load_tile_async(st + 0 * TILE_BYTES, Ahi, bm, 0, tid);
        load_tile_async(st + 1 * TILE_BYTES, Alo, bm, 0, tid);
        load_tile_async(st + 2 * TILE_BYTES, Whi, bn, 0, tid);
        load_tile_async(st + 3 * TILE_BYTES, Wlo, bn, 0, tid);
        CP_ASYNC_COMMIT();
    }

    for (int ck = 0; ck < NC; ck++) {
        CP_ASYNC_WAIT(0);
        __syncthreads();   // data for stage ck visible; stage ck^1's readers done

        if (ck + 1 < NC) {
            uint32_t st = sbase + (uint32_t)((ck + 1) & 1) * STAGE_BYTES;
            int k0 = (ck + 1) * 32;
            load_tile_async(st + 0 * TILE_BYTES, Ahi, bm, k0, tid);
            load_tile_async(st + 1 * TILE_BYTES, Alo, bm, k0, tid);
            load_tile_async(st + 2 * TILE_BYTES, Whi, bn, k0, tid);
            load_tile_async(st + 3 * TILE_BYTES, Wlo, bn, k0, tid);
            CP_ASYNC_COMMIT();
        }

        const uint32_t st  = sbase + (uint32_t)(ck & 1) * STAGE_BYTES;
        const uint32_t sAh = st + 0 * TILE_BYTES;
        const uint32_t sAl = st + 1 * TILE_BYTES;
        const uint32_t sWh = st + 2 * TILE_BYTES;
        const uint32_t sWl = st + 3 * TILE_BYTES;

        #pragma unroll
        for (int kk = 0; kk < 2; kk++) {
            const int kc = kk * 16;
            uint32_t ah[2][4], al[2][4];
            #pragma unroll
            for (int mi = 0; mi < 2; mi++) {
                int r = wm0 + mi * 16 + (lane & 15);
                int c = kc + ((lane >> 4) << 3);
                uint32_t off = (uint32_t)(r * (RS_G * 2) + c * 2);
                ldsm_x4(sAh + off, ah[mi]);
                ldsm_x4(sAl + off, al[mi]);
            }
            #pragma unroll
            for (int p = 0; p < 4; p++) {
                int r = wn0 + p * 16 + (lane & 7) + ((lane >> 4) & 1) * 8;
                int c = kc + ((lane >> 3) & 1) * 8;
                uint32_t off = (uint32_t)(r * (RS_G * 2) + c * 2);
                uint32_t wh[4], wl[4];
                ldsm_x4(sWh + off, wh);
                ldsm_x4(sWl + off, wl);
                #pragma unroll
                for (int mi = 0; mi < 2; mi++) {
                    mma_bf16(acc[mi][2 * p],     ah[mi], wh + 0);
                    mma_bf16(acc[mi][2 * p + 1], ah[mi], wh + 2);
                    mma_bf16(acc[mi][2 * p],     ah[mi], wl + 0);
                    mma_bf16(acc[mi][2 * p + 1], ah[mi], wl + 2);
                    mma_bf16(acc[mi][2 * p],     al[mi], wh + 0);
                    mma_bf16(acc[mi][2 * p + 1], al[mi], wh + 2);
                }
            }
        }
        __syncthreads();   // all warps done with stage ck before its reload
    }
}

// NOTE on the loop above: the trailing barrier is required because the loads
// for chunk ck+2 (issued at top of iteration ck+1) reuse stage ck&1. With the
// issue-after-sync ordering, iteration ck+1's loads target stage (ck+2)&1 ==
// ck&1 only at ck+2; the sync at top of ck+1 only proves compute of ck started,
// not finished. Keeping one barrier at the end and ONE at the top would be two
// again — instead we rely on: top-of-loop sync proves *previous* compute fully
// done (it is the same barrier instance). To make that true, the compute must
// finish before the next top-of-loop sync — which the trailing barrier
// guarantees while still overlapping cp.async (issued pre-compute) with compute.
// Net effect: loads overlap compute fully; barrier count unchanged at the top
// but the WAIT no longer sits between barriers, removing the serialization
// bubble.

// ---------- fused QKV projection: z selects {q,k,v}; v stored transposed ----
__global__ __launch_bounds__(256, 2) void gemm_qkv(
    const __nv_bfloat16* __restrict__ Ahi, const __nv_bfloat16* __restrict__ Alo,
    const __nv_bfloat16* __restrict__ Wh,  const __nv_bfloat16* __restrict__ Wl,
    const float* __restrict__ b0, const float* __restrict__ b1,
    const float* __restrict__ b2,
    __nv_bfloat16* __restrict__ qh, __nv_bfloat16* __restrict__ ql,
    __nv_bfloat16* __restrict__ kh, __nv_bfloat16* __restrict__ kl,
    __nv_bfloat16* __restrict__ vh, __nv_bfloat16* __restrict__ vl)
{
    extern __shared__ __align__(16) char smem[];
    const uint32_t sbase = smem_u32(smem);
    const int tid = threadIdx.x;
    const int bm  = blockIdx.y * 128;
    const int bn  = blockIdx.x * 128;
    const int z   = blockIdx.z;
    const int nW  = C_ * C_;

    const float* bias = (z == 0) ? b0 : (z == 1) ? b1 : b2;
    __nv_bfloat16* ohi = (z == 0) ? qh : (z == 1) ? kh : vh;
    __nv_bfloat16* olo = (z == 0) ? ql : (z == 1) ? kl : vl;

    float acc[2][8][4];
    #pragma unroll
    for (int mi = 0; mi < 2; mi++)
        #pragma unroll
        for (int ni = 0; ni < 8; ni++)
            #pragma unroll
            for (int t = 0; t < 4; t++) acc[mi][ni][t] = 0.f;

    gemm_mainloop(sbase, Ahi, Alo, Wh + (size_t)z * nW, Wl + (size_t)z * nW,
                  bm, bn, tid, acc);

    const int lane = tid & 31;
    const int w    = tid >> 5;
    const int wm0  = (w & 3) * 32;
    const int wn0  = (w >> 2) * 64;

    #pragma unroll
    for (int mi = 0; mi < 2; mi++) {
        #pragma unroll
        for (int ni = 0; ni < 8; ni++) {
            int row0 = bm + wm0 + mi * 16 + (lane >> 2);
            int col  = bn + wn0 + ni * 8 + (lane & 3) * 2;
            float bb0 = bias[col], bb1 = bias[col + 1];
            float v00 = acc[mi][ni][0] + bb0, v01 = acc[mi][ni][1] + bb1;
            float v10 = acc[mi][ni][2] + bb0, v11 = acc[mi][ni][3] + bb1;
            int h = col >> 6, d = col & 63;
            if (z < 2) {   // [B,H,T,hd]
                uint32_t hh, ll;
                {
                    int b = row0 >> 11, t = row0 & 2047;
                    size_t o = ((size_t)((b * H_ + h) * T_ + t)) * HD + d;
                    psplit(v00, v01, hh, ll);
                    *(uint32_t*)(ohi + o) = hh; *(uint32_t*)(olo + o) = ll;
                }
                {
                    int r1 = row0 + 8;
                    int b = r1 >> 11, t = r1 & 2047;
                    size_t o = ((size_t)((b * H_ + h) * T_ + t)) * HD + d;
                    psplit(v10, v11, hh, ll);
                    *(uint32_t*)(ohi + o) = hh; *(uint32_t*)(olo + o) = ll;
                }
            } else {       // V transposed [B,H,hd,T]
                int b = row0 >> 11, t = row0 & 2047;
                int bhh = b * H_ + h;
                size_t base0 = ((size_t)(bhh * HD + d)) * T_;
                size_t base1 = ((size_t)(bhh * HD + d + 1)) * T_;
                __nv_bfloat16 h00 = __float2bfloat16_rn(v00);
                __nv_bfloat16 h01 = __float2bfloat16_rn(v01);
                __nv_bfloat16 h10 = __float2bfloat16_rn(v10);
                __nv_bfloat16 h11 = __float2bfloat16_rn(v11);
                ohi[base0 + t]     = h00;
                ohi[base1 + t]     = h01;
                ohi[base0 + t + 8] = h10;
                ohi[base1 + t + 8] = h11;
                olo[base0 + t]     = __float2bfloat16_rn(v00 - __bfloat162float(h00));
                olo[base1 + t]     = __float2bfloat16_rn(v01 - __bfloat162float(h01));
                olo[base0 + t + 8] = __float2bfloat16_rn(v10 - __bfloat162float(h10));
                olo[base1 + t + 8] = __float2bfloat16_rn(v11 - __bfloat162float(h11));
            }
        }
    }
}

// ---------- O-projection: fp32 row-major output ----------
__global__ __launch_bounds__(256, 2) void gemm_out(
    const __nv_bfloat16* __restrict__ Ahi, const __nv_bfloat16* __restrict__ Alo,
    const __nv_bfloat16* __restrict__ Whi, const __nv_bfloat16* __restrict__ Wlo,
    const float* __restrict__ bias, float* __restrict__ out)
{
    extern __shared__ __align__(16) char smem[];
    const uint32_t sbase = smem_u32(smem);
    const int tid = threadIdx.x;
    const int bm  = blockIdx.y * 128;
    const int bn  = blockIdx.x * 128;

    float acc[2][8][4];
    #pragma unroll
    for (int mi = 0; mi < 2; mi++)
        #pragma unroll
        for (int ni = 0; ni < 8; ni++)
            #pragma unroll
            for (int t = 0; t < 4; t++) acc[mi][ni][t] = 0.f;

    gemm_mainloop(sbase, Ahi, Alo, Whi, Wlo, bm, bn, tid, acc);

    const int lane = tid & 31;
    const int w    = tid >> 5;
    const int wm0  = (w & 3) * 32;
    const int wn0  = (w >> 2) * 64;

    #pragma unroll
    for (int mi = 0; mi < 2; mi++) {
        #pragma unroll
        for (int ni = 0; ni < 8; ni++) {
            int row0 = bm + wm0 + mi * 16 + (lane >> 2);
            int col  = bn + wn0 + ni * 8 + (lane & 3) * 2;
            float b0 = bias[col], b1 = bias[col + 1];
            float2 a; a.x = acc[mi][ni][0] + b0; a.y = acc[mi][ni][1] + b1;
            float2 c; c.x = acc[mi][ni][2] + b0; c.y = acc[mi][ni][3] + b1;
            *(float2*)&out[(size_t)row0 * C_ + col]       = a;
            *(float2*)&out[(size_t)(row0 + 8) * C_ + col] = c;
        }
    }
}

// =============================================================================
// Tensor-core flash attention (causal). Longest q-tiles first; single-sync
// double-buffered KV pipeline.
// =============================================================================
constexpr int ARS       = 72;
constexpr int QS_BYTES  = 128 * ARS * 2;
constexpr int KVT_BYTES = 64 * ARS * 2;
constexpr int ATT_SMEM  = 2 * QS_BYTES + 2 * 4 * KVT_BYTES;

__device__ __forceinline__ void att_load_kv(
    uint32_t sKh, uint32_t sKl, uint32_t sVh, uint32_t sVl,
    const __nv_bfloat16* __restrict__ khi, const __nv_bfloat16* __restrict__ klo,
    const __nv_bfloat16* __restrict__ vthi, const __nv_bfloat16* __restrict__ vtlo,
    int bh, int k0, int tid)
{
    #pragma unroll
    for (int it = 0; it < 2; it++) {
        int id  = tid + it * 256;
        int row = id >> 3;
        int ch  = id & 7;
        uint32_t so = (uint32_t)(row * (ARS * 2) + ch * 16);
        size_t goK = ((size_t)(bh * T_ + k0 + row) * HD + ch * 8) * 2;
        cp_async16(sKh + so, (const char*)khi + goK);
        cp_async16(sKl + so, (const char*)klo + goK);
        size_t goV = ((size_t)(bh * HD + row) * T_ + k0 + ch * 8) * 2;
        cp_async16(sVh + so, (const char*)vthi + goV);
        cp_async16(sVl + so, (const char*)vtlo + goV);
    }
}

__global__ __launch_bounds__(256, 1) void attn_tc(
    const __nv_bfloat16* __restrict__ qhi, const __nv_bfloat16* __restrict__ qlo,
    const __nv_bfloat16* __restrict__ khi, const __nv_bfloat16* __restrict__ klo,
    const __nv_bfloat16* __restrict__ vthi, const __nv_bfloat16* __restrict__ vtlo,
    __nv_bfloat16* __restrict__ out_hi, __nv_bfloat16* __restrict__ out_lo)
{
    extern __shared__ __align__(16) char smem[];
    const uint32_t sb  = smem_u32(smem);
    const uint32_t sQh = sb, sQl = sb + QS_BYTES;
    const int tid  = threadIdx.x;
    const int lane = tid & 31;
    const int w    = tid >> 5;
    const int bh   = blockIdx.x;
    const int qi   = (int)gridDim.y - 1 - (int)blockIdx.y;  // longest first
    const int q0   = qi * 128;
    const int ktmax = 2 * qi + 1;
    const float SC = 0.18033688011112042f;   // hd^-0.5 * log2(e)

    #pragma unroll
    for (int it = 0; it < 4; it++) {
        int id  = tid + it * 256;
        int row = id >> 3;
        int ch  = id & 7;
        uint32_t so = (uint32_t)(row * (ARS * 2) + ch * 16);
        size_t go = ((size_t)(bh * T_ + q0 + row) * HD + ch * 8) * 2;
        cp_async16(sQh + so, (const char*)qhi + go);
        cp_async16(sQl + so, (const char*)qlo + go);
    }
    {
        uint32_t skv = sb + 2 * QS_BYTES;
        att_load_kv(skv, skv + KVT_BYTES, skv + 2 * KVT_BYTES, skv + 3 * KVT_BYTES,
                    khi, klo, vthi, vtlo, bh, 0, tid);
    }
    CP_ASYNC_COMMIT();

    float o[8][4];
    #pragma unroll
    for (int n = 0; n < 8; n++)
        #pragma unroll
        for (int t = 0; t < 4; t++) o[n][t] = 0.f;
    float m0 = -1e30f, m1 = -1e30f, l0 = 0.f, l1 = 0.f;
    uint32_t qfh[4][4], qfl[4][4];

    const int rlo_base = q0 + w * 16 + (lane >> 2);

    for (int kt = 0; kt <= ktmax; kt++) {
        const int s = kt & 1;
        CP_ASYNC_WAIT(0);
        __syncthreads();   // stage s data visible; stage s^1 readers (kt-1) done

        if (kt == 0) {
            #pragma unroll
            for (int kc = 0; kc < 4; kc++) {
                uint32_t off = (uint32_t)((w * 16 + (lane & 15)) * (ARS * 2)
                                          + kc * 32 + ((lane >> 4) << 4));
                ldsm_x4(sQh + off, qfh[kc]);
                ldsm_x4(sQl + off, qfl[kc]);
            }
        }

        if (kt + 1 <= ktmax) {
            uint32_t skv = sb + 2 * QS_BYTES + (uint32_t)(s ^ 1) * 4 * KVT_BYTES;
            att_load_kv(skv, skv + KVT_BYTES, skv + 2 * KVT_BYTES, skv + 3 * KVT_BYTES,
                        khi, klo, vthi, vtlo, bh, (kt + 1) * 64, tid);
            CP_ASYNC_COMMIT();
        }

        bool active = (kt * 64 <= q0 + w * 16 + 15);

        if (active) {
            const uint32_t skv = sb + 2 * QS_BYTES + (uint32_t)s * 4 * KVT_BYTES;
            const uint32_t sKh = skv, sKl = skv + KVT_BYTES;
            const uint32_t sVh = skv + 2 * KVT_BYTES, sVl = skv + 3 * KVT_BYTES;

            float sv[8][4];
            #pragma unroll
            for (int n = 0; n < 8; n++)
                #pragma unroll
                for (int t = 0; t < 4; t++) sv[n][t] = 0.f;

            #pragma unroll
            for (int kc = 0; kc < 4; kc++) {
                uint32_t kh[8][2], kl[8][2];
                #pragma unroll
                for (int p = 0; p < 4; p++) {
                    uint32_t off = (uint32_t)((p * 16 + (lane & 7) + ((lane >> 4) & 1) * 8)
                                              * (ARS * 2) + kc * 32 + ((lane >> 3) & 1) * 16);
                    uint32_t tmp[4];
                    ldsm_x4(sKh + off, tmp);
                    kh[2 * p][0] = tmp[0]; kh[2 * p][1] = tmp[1];
                    kh[2 * p + 1][0] = tmp[2]; kh[2 * p + 1][1] = tmp[3];
                    ldsm_x4(sKl + off, tmp);
                    kl[2 * p][0] = tmp[0]; kl[2 * p][1] = tmp[1];
                    kl[2 * p + 1][0] = tmp[2]; kl[2 * p + 1][1] = tmp[3];
                }
                #pragma unroll
                for (int n = 0; n < 8; n++) mma_bf16(sv[n], qfh[kc], kh[n]);
                #pragma unroll
                for (int n = 0; n < 8; n++) mma_bf16(sv[n], qfh[kc], kl[n]);
                #pragma unroll
                for (int n = 0; n < 8; n++) mma_bf16(sv[n], qfl[kc], kh[n]);
            }

            const int rlo = rlo_base;
            const int rhi = rlo + 8;
            const bool needmask = (kt * 64 + 63 > q0 + w * 16);
            float mx0 = m0, mx1 = m1;
            #pragma unroll
            for (int n = 0; n < 8; n++) {
                int j = kt * 64 + n * 8 + (lane & 3) * 2;
                sv[n][0] *= SC; sv[n][1] *= SC; sv[n][2] *= SC; sv[n][3] *= SC;
                if (needmask) {
                    if (j     > rlo) sv[n][0] = -1e30f;
                    if (j + 1 > rlo) sv[n][1] = -1e30f;
                    if (j     > rhi) sv[n][2] = -1e30f;
                    if (j + 1 > rhi) sv[n][3] = -1e30f;
                }
                mx0 = fmaxf(mx0, fmaxf(sv[n][0], sv[n][1]));
                mx1 = fmaxf(mx1, fmaxf(sv[n][2], sv[n][3]));
            }
            mx0 = fmaxf(mx0, __shfl_xor_sync(0xffffffffu, mx0, 1));
            mx0 = fmaxf(mx0, __shfl_xor_sync(0xffffffffu, mx0, 2));
            mx1 = fmaxf(mx1, __shfl_xor_sync(0xffffffffu, mx1, 1));
            mx1 = fmaxf(mx1, __shfl_xor_sync(0xffffffffu, mx1, 2));
            const float a0 = ex2f(m0 - mx0);
            const float a1 = ex2f(m1 - mx1);
            m0 = mx0; m1 = mx1;

            float sum0 = 0.f, sum1 = 0.f;
            #pragma unroll
            for (int n = 0; n < 8; n++) {
                sv[n][0] = ex2f(sv[n][0] - mx0);
                sv[n][1] = ex2f(sv[n][1] - mx0);
                sv[n][2] = ex2f(sv[n][2] - mx1);
                sv[n][3] = ex2f(sv[n][3] - mx1);
                sum0 += sv[n][0] + sv[n][1];
                sum1 += sv[n][2] + sv[n][3];
            }
            l0 = l0 * a0 + sum0;
            l1 = l1 * a1 + sum1;
            #pragma unroll
            for (int n = 0; n < 8; n++) {
                o[n][0] *= a0; o[n][1] *= a0; o[n][2] *= a1; o[n][3] *= a1;
            }

            uint32_t ph[4][4], pl[4][4];
            #pragma unroll
            for (int kc = 0; kc < 4; kc++) {
                psplit(sv[2 * kc][0],     sv[2 * kc][1],     ph[kc][0], pl[kc][0]);
                psplit(sv[2 * kc][2],     sv[2 * kc][3],     ph[kc][1], pl[kc][1]);
                psplit(sv[2 * kc + 1][0], sv[2 * kc + 1][1], ph[kc][2], pl[kc][2]);
                psplit(sv[2 * kc + 1][2], sv[2 * kc + 1][3], ph[kc][3], pl[kc][3]);
            }

            #pragma unroll
            for (int kc = 0; kc < 4; kc++) {
                uint32_t vh[8][2], vl[8][2];
                #pragma unroll
                for (int p = 0; p < 4; p++) {
                    uint32_t off = (uint32_t)((p * 16 + (lane & 7) + ((lane >> 4) & 1) * 8)
                                              * (ARS * 2) + kc * 32 + ((lane >> 3) & 1) * 16);
                    uint32_t tmp[4];
                    ldsm_x4(sVh + off, tmp);
                    vh[2 * p][0] = tmp[0]; vh[2 * p][1] = tmp[1];
                    vh[2 * p + 1][0] = tmp[2]; vh[2 * p + 1][1] = tmp[3];
                    ldsm_x4(sVl + off, tmp);
                    vl[2 * p][0] = tmp[0]; vl[2 * p][1] = tmp[1];
                    vl[2 * p + 1][0] = tmp[2]; vl[2 * p + 1][1] = tmp[3];
                }
                #pragma unroll
                for (int n = 0; n < 8; n++) mma_bf16(o[n], ph[kc], vh[n]);
                #pragma unroll
                for (int n = 0; n < 8; n++) mma_bf16(o[n], ph[kc], vl[n]);
                #pragma unroll
                for (int n = 0; n < 8; n++) mma_bf16(o[n], pl[kc], vh[n]);
            }
        }
        __syncthreads();   // all warps done reading stage s before it reloads
    }

    l0 += __shfl_xor_sync(0xffffffffu, l0, 1);
    l0 += __shfl_xor_sync(0xffffffffu, l0, 2);
    l1 += __shfl_xor_sync(0xffffffffu, l1, 1);
    l1 += __shfl_xor_sync(0xffffffffu, l1, 2);
    const float inv0 = 1.f / l0;
    const float inv1 = 1.f / l1;

    const int b = bh >> 4, h = bh & 15;
    const int t0 = q0 + w * 16 + (lane >> 2);
    const int t1 = t0 + 8;
    #pragma unroll
    for (int n = 0; n < 8; n++) {
        int d = n * 8 + (lane & 3) * 2;
        uint32_t hh, ll;
        size_t o0 = ((size_t)(b * T_ + t0)) * C_ + h * HD + d;
        psplit(o[n][0] * inv0, o[n][1] * inv0, hh, ll);
        *(uint32_t*)(out_hi + o0) = hh;
        *(uint32_t*)(out_lo + o0) = ll;
        size_t o1 = ((size_t)(b * T_ + t1)) * C_ + h * HD + d;
        psplit(o[n][2] * inv1, o[n][3] * inv1, hh, ll);
        *(uint32_t*)(out_hi + o1) = hh;
        *(uint32_t*)(out_lo + o1) = ll;
    }
}

// =============================================================================
extern "C" void kernel_launch(void* const* d_in, const int* in_sizes, int n_in,
                              void* d_out, int out_size)
{
    (void)in_sizes; (void)n_in; (void)out_size;
    const float* x  = (const float*)d_in[0];
    const float* wq = (const float*)d_in[1];
    const float* bq = (const float*)d_in[2];
    const float* wk = (const float*)d_in[3];
    const float* bk = (const float*)d_in[4];
    const float* wv = (const float*)d_in[5];
    const float* bv = (const float*)d_in[6];
    const float* wo = (const float*)d_in[7];
    const float* bo = (const float*)d_in[8];
    float* out = (float*)d_out;

    __nv_bfloat16 *ahi, *alo, *whi, *wlo;
    __nv_bfloat16 *qhi, *qlo, *khi, *klo, *vthi, *vtlo;
    cudaGetSymbolAddress((void**)&ahi,  g_ahi);
    cudaGetSymbolAddress((void**)&alo,  g_alo);
    cudaGetSymbolAddress((void**)&whi,  g_whi);
    cudaGetSymbolAddress((void**)&wlo,  g_wlo);
    cudaGetSymbolAddress((void**)&qhi,  g_qhi);
    cudaGetSymbolAddress((void**)&qlo,  g_qlo);
    cudaGetSymbolAddress((void**)&khi,  g_khi);
    cudaGetSymbolAddress((void**)&klo,  g_klo);
    cudaGetSymbolAddress((void**)&vthi, g_vthi);
    cudaGetSymbolAddress((void**)&vtlo, g_vtlo);

    const int nW = C_ * C_;

    // one fused split launch: x + 4 weight matrices
    split_all<<<12288, 256>>>(x, wq, wk, wv, wo, ahi, alo, whi, wlo);

    cudaFuncSetAttribute(gemm_qkv, cudaFuncAttributeMaxDynamicSharedMemorySize, GEMM_SMEM);
    cudaFuncSetAttribute(gemm_out, cudaFuncAttributeMaxDynamicSharedMemorySize, GEMM_SMEM);
    cudaFuncSetAttribute(attn_tc,  cudaFuncAttributeMaxDynamicSharedMemorySize, ATT_SMEM);

    // fused QKV projections (z = 0,1,2)
    gemm_qkv<<<dim3(C_ / 128, M_ / 128, 3), 256, GEMM_SMEM>>>(
        ahi, alo, whi, wlo, bq, bk, bv, qhi, qlo, khi, klo, vthi, vtlo);

    // attention overwrites ahi/alo with split attention output
    attn_tc<<<dim3(B_ * H_, T_ / 128), 256, ATT_SMEM>>>(qhi, qlo, khi, klo,
                                                        vthi, vtlo, ahi, alo);

    gemm_out<<<dim3(C_ / 128, M_ / 128), 256, GEMM_SMEM>>>(
        ahi, alo, whi + 3 * nW, wlo + 3 * nW, bo, out);
}

// round 9
// speedup vs baseline: 3.2260x; 1.0041x over previous
#include <cuda_runtime.h>
#include <cuda_bf16.h>
#include <math.h>
#include <stdint.h>

// Problem constants
constexpr int B_  = 4;
constexpr int T_  = 2048;
constexpr int C_  = 1024;
constexpr int H_  = 16;
constexpr int HD  = 64;
constexpr int M_  = B_ * T_;

// -------------------- scratch (static device allocations) --------------------
__device__ __nv_bfloat16 g_ahi[M_ * C_];     // activations hi (x, later attn-out)
__device__ __nv_bfloat16 g_alo[M_ * C_];
__device__ __nv_bfloat16 g_whi[4 * C_ * C_]; // weights hi (q,k,v,o)
__device__ __nv_bfloat16 g_wlo[4 * C_ * C_];
__device__ __nv_bfloat16 g_qhi[B_ * H_ * T_ * HD];  // [B,H,T,hd]
__device__ __nv_bfloat16 g_qlo[B_ * H_ * T_ * HD];
__device__ __nv_bfloat16 g_khi[B_ * H_ * T_ * HD];
__device__ __nv_bfloat16 g_klo[B_ * H_ * T_ * HD];
__device__ __nv_bfloat16 g_vthi[B_ * H_ * HD * T_]; // [B,H,hd,T] (transposed)
__device__ __nv_bfloat16 g_vtlo[B_ * H_ * HD * T_];

// =============================================================================
// helpers (compute_103-portable)
// =============================================================================
__device__ __forceinline__ uint32_t smem_u32(const void* p) {
    uint32_t a;
    asm("{ .reg .u64 t; cvta.to.shared.u64 t, %1; cvt.u32.u64 %0, t; }"
        : "=r"(a) : "l"(p));
    return a;
}
__device__ __forceinline__ void ldsm_x4(uint32_t addr, uint32_t* r) {
    asm volatile("ldmatrix.sync.aligned.m8n8.x4.shared.b16 {%0,%1,%2,%3}, [%4];"
                 : "=r"(r[0]), "=r"(r[1]), "=r"(r[2]), "=r"(r[3]) : "r"(addr));
}
__device__ __forceinline__ void mma_bf16(float* d, const uint32_t* a, const uint32_t* b) {
    asm volatile(
        "mma.sync.aligned.m16n8k16.row.col.f32.bf16.bf16.f32 "
        "{%0,%1,%2,%3}, {%4,%5,%6,%7}, {%8,%9}, {%0,%1,%2,%3};"
        : "+f"(d[0]), "+f"(d[1]), "+f"(d[2]), "+f"(d[3])
        : "r"(a[0]), "r"(a[1]), "r"(a[2]), "r"(a[3]), "r"(b[0]), "r"(b[1]));
}
__device__ __forceinline__ void cp_async16(uint32_t dst, const void* src) {
    asm volatile("cp.async.cg.shared.global [%0], [%1], 16;" :: "r"(dst), "l"(src));
}
#define CP_ASYNC_COMMIT() asm volatile("cp.async.commit_group;" ::: "memory")
#define CP_ASYNC_WAIT(n)  asm volatile("cp.async.wait_group %0;" :: "n"(n) : "memory")

__device__ __forceinline__ float ex2f(float x) {
    float y;
    asm("ex2.approx.ftz.f32 %0, %1;" : "=f"(y) : "f"(x));
    return y;
}
// pack (x,y) -> bf16x2 hi + bf16x2 lo residual
__device__ __forceinline__ void psplit(float x, float y, uint32_t& hi, uint32_t& lo) {
    __nv_bfloat162 h = __floats2bfloat162_rn(x, y);
    float rx = x - __bfloat162float(h.x);
    float ry = y - __bfloat162float(h.y);
    __nv_bfloat162 l = __floats2bfloat162_rn(rx, ry);
    hi = *(uint32_t*)&h;
    lo = *(uint32_t*)&l;
}

// =============================================================================
// fused split: fp32 -> bf16 hi + lo for x and all 4 weight matrices, 1 launch
// =============================================================================
__global__ __launch_bounds__(256) void split_all(
    const float* __restrict__ x,
    const float* __restrict__ wq, const float* __restrict__ wk,
    const float* __restrict__ wv, const float* __restrict__ wo,
    __nv_bfloat16* __restrict__ ahi, __nv_bfloat16* __restrict__ alo,
    __nv_bfloat16* __restrict__ whi, __nv_bfloat16* __restrict__ wlo)
{
    const int nW = C_ * C_;
    int blk = blockIdx.x;
    const float* src;
    __nv_bfloat16 *hi, *lo;
    int base;
    if (blk < 8192) {
        src = x; hi = ahi; lo = alo; base = blk;
    } else {
        int r = blk - 8192;
        int ws = r >> 10;          // 0..3
        base = r & 1023;
        src = (ws == 0) ? wq : (ws == 1) ? wk : (ws == 2) ? wv : wo;
        hi = whi + (size_t)ws * nW;
        lo = wlo + (size_t)ws * nW;
    }
    int i = (base * 256 + threadIdx.x) * 4;
    float4 v = *(const float4*)(src + i);
    uint32_t h0, l0, h1, l1;
    psplit(v.x, v.y, h0, l0);
    psplit(v.z, v.w, h1, l1);
    *(uint32_t*)(hi + i)     = h0;
    *(uint32_t*)(hi + i + 2) = h1;
    *(uint32_t*)(lo + i)     = l0;
    *(uint32_t*)(lo + i + 2) = l1;
}

// =============================================================================
// GEMM mainloop: acc = A[M,K] @ W[N,K]^T, split-bf16 x3, fp32 accum.
// CTA 128x128, BK=32, 8 warps (4m x 2n), 2-stage cp.async, 2 CTAs/SM.
// Register-level ping-pong pipeline: W-fragments for (kk,p)+1 are ldsm'd
// BEFORE the 12 MMAs of (kk,p), giving each ldsm ~12 MMAs of latency cover.
// =============================================================================
constexpr int RS_G        = 40;
constexpr int TILE_BYTES  = 128 * RS_G * 2;          // 10240
constexpr int STAGE_BYTES = 4 * TILE_BYTES;          // 40960
constexpr int GEMM_SMEM   = 2 * STAGE_BYTES;         // 81920

__device__ __forceinline__ void load_tile_async(
    uint32_t dst, const __nv_bfloat16* __restrict__ src,
    int rowbase, int k0, int tid)
{
    #pragma unroll
    for (int it = 0; it < 2; it++) {
        int id   = tid + it * 256;
        int row  = id >> 2;
        int quad = id & 3;
        cp_async16(dst + (uint32_t)(row * (RS_G * 2) + quad * 16),
                   (const char*)src +
                   ((size_t)(rowbase + row) * C_ + (size_t)k0 + quad * 8) * 2);
    }
}

__device__ __forceinline__ void gemm_mainloop(
    uint32_t sbase,
    const __nv_bfloat16* __restrict__ Ahi, const __nv_bfloat16* __restrict__ Alo,
    const __nv_bfloat16* __restrict__ Whi, const __nv_bfloat16* __restrict__ Wlo,
    int bm, int bn, int tid, float acc[2][8][4])
{
    const int lane = tid & 31;
    const int w    = tid >> 5;
    const int wm0  = (w & 3) * 32;
    const int wn0  = (w >> 2) * 64;
    constexpr int NC = C_ / 32;

    // lane-fixed ldsm address bases (bytes)
    const uint32_t aOffB = (uint32_t)((wm0 + (lane & 15)) * (RS_G * 2)
                                      + ((lane >> 4) << 4));
    const uint32_t wOffB = (uint32_t)((wn0 + (lane & 7) + ((lane >> 4) & 1) * 8)
                                      * (RS_G * 2) + ((lane >> 3) & 1) * 16);
    // (kk,p) deltas: +kk*32 bytes (16 cols), +p*16 rows, +mi*16 rows

    {
        uint32_t st = sbase;
        load_tile_async(st + 0 * TILE_BYTES, Ahi, bm, 0, tid);
        load_tile_async(st + 1 * TILE_BYTES, Alo, bm, 0, tid);
        load_tile_async(st + 2 * TILE_BYTES, Whi, bn, 0, tid);
        load_tile_async(st + 3 * TILE_BYTES, Wlo, bn, 0, tid);
        CP_ASYNC_COMMIT();
    }

    for (int ck = 0; ck < NC; ck++) {
        CP_ASYNC_WAIT(0);
        __syncthreads();   // stage ck visible; stage ck^1's readers done

        if (ck + 1 < NC) {
            uint32_t st = sbase + (uint32_t)((ck + 1) & 1) * STAGE_BYTES;
            int k0 = (ck + 1) * 32;
            load_tile_async(st + 0 * TILE_BYTES, Ahi, bm, k0, tid);
            load_tile_async(st + 1 * TILE_BYTES, Alo, bm, k0, tid);
            load_tile_async(st + 2 * TILE_BYTES, Whi, bn, k0, tid);
            load_tile_async(st + 3 * TILE_BYTES, Wlo, bn, k0, tid);
            CP_ASYNC_COMMIT();
        }

        const uint32_t st  = sbase + (uint32_t)(ck & 1) * STAGE_BYTES;
        const uint32_t sAh = st + 0 * TILE_BYTES;
        const uint32_t sAl = st + 1 * TILE_BYTES;
        const uint32_t sWh = st + 2 * TILE_BYTES;
        const uint32_t sWl = st + 3 * TILE_BYTES;

        // W ping-pong buffers: [buf][hi/lo][4 regs]; x4 covers n-tiles 2p,2p+1
        uint32_t wb[2][2][4];
        ldsm_x4(sWh + wOffB, wb[0][0]);      // prefetch (kk=0,p=0)
        ldsm_x4(sWl + wOffB, wb[0][1]);
        int cur = 0;

        #pragma unroll
        for (int kk = 0; kk < 2; kk++) {
            uint32_t ah[2][4], al[2][4];
            #pragma unroll
            for (int mi = 0; mi < 2; mi++) {
                uint32_t off = aOffB + (uint32_t)(mi * 16 * (RS_G * 2) + kk * 32);
                ldsm_x4(sAh + off, ah[mi]);
                ldsm_x4(sAl + off, al[mi]);
            }
            #pragma unroll
            for (int p = 0; p < 4; p++) {
                const int s = kk * 4 + p;
                if (s < 7) {  // prefetch next (kk,p) W fragments
                    const int sn = s + 1;
                    const int kn = sn >> 2, pn = sn & 3;
                    uint32_t off = wOffB + (uint32_t)(pn * 16 * (RS_G * 2) + kn * 32);
                    ldsm_x4(sWh + off, wb[cur ^ 1][0]);
                    ldsm_x4(sWl + off, wb[cur ^ 1][1]);
                }
                const uint32_t* wh = wb[cur][0];
                const uint32_t* wl = wb[cur][1];
                #pragma unroll
                for (int mi = 0; mi < 2; mi++) {
                    mma_bf16(acc[mi][2 * p],     ah[mi], wh + 0);
                    mma_bf16(acc[mi][2 * p + 1], ah[mi], wh + 2);
                    mma_bf16(acc[mi][2 * p],     ah[mi], wl + 0);
                    mma_bf16(acc[mi][2 * p + 1], ah[mi], wl + 2);
                    mma_bf16(acc[mi][2 * p],     al[mi], wh + 0);
                    mma_bf16(acc[mi][2 * p + 1], al[mi], wh + 2);
                }
                cur ^= 1;
            }
        }
        __syncthreads();   // all warps done with stage ck before its reload
    }
}

// ---------- fused QKV projection: z selects {q,k,v}; v stored transposed ----
__global__ __launch_bounds__(256, 2) void gemm_qkv(
    const __nv_bfloat16* __restrict__ Ahi, const __nv_bfloat16* __restrict__ Alo,
    const __nv_bfloat16* __restrict__ Wh,  const __nv_bfloat16* __restrict__ Wl,
    const float* __restrict__ b0, const float* __restrict__ b1,
    const float* __restrict__ b2,
    __nv_bfloat16* __restrict__ qh, __nv_bfloat16* __restrict__ ql,
    __nv_bfloat16* __restrict__ kh, __nv_bfloat16* __restrict__ kl,
    __nv_bfloat16* __restrict__ vh, __nv_bfloat16* __restrict__ vl)
{
    extern __shared__ __align__(16) char smem[];
    const uint32_t sbase = smem_u32(smem);
    const int tid = threadIdx.x;
    const int bm  = blockIdx.y * 128;
    const int bn  = blockIdx.x * 128;
    const int z   = blockIdx.z;
    const int nW  = C_ * C_;

    const float* bias = (z == 0) ? b0 : (z == 1) ? b1 : b2;
    __nv_bfloat16* ohi = (z == 0) ? qh : (z == 1) ? kh : vh;
    __nv_bfloat16* olo = (z == 0) ? ql : (z == 1) ? kl : vl;

    float acc[2][8][4];
    #pragma unroll
    for (int mi = 0; mi < 2; mi++)
        #pragma unroll
        for (int ni = 0; ni < 8; ni++)
            #pragma unroll
            for (int t = 0; t < 4; t++) acc[mi][ni][t] = 0.f;

    gemm_mainloop(sbase, Ahi, Alo, Wh + (size_t)z * nW, Wl + (size_t)z * nW,
                  bm, bn, tid, acc);

    const int lane = tid & 31;
    const int w    = tid >> 5;
    const int wm0  = (w & 3) * 32;
    const int wn0  = (w >> 2) * 64;

    #pragma unroll
    for (int mi = 0; mi < 2; mi++) {
        #pragma unroll
        for (int ni = 0; ni < 8; ni++) {
            int row0 = bm + wm0 + mi * 16 + (lane >> 2);
            int col  = bn + wn0 + ni * 8 + (lane & 3) * 2;
            float bb0 = bias[col], bb1 = bias[col + 1];
            float v00 = acc[mi][ni][0] + bb0, v01 = acc[mi][ni][1] + bb1;
            float v10 = acc[mi][ni][2] + bb0, v11 = acc[mi][ni][3] + bb1;
            int h = col >> 6, d = col & 63;
            if (z < 2) {   // [B,H,T,hd]
                uint32_t hh, ll;
                {
                    int b = row0 >> 11, t = row0 & 2047;
                    size_t o = ((size_t)((b * H_ + h) * T_ + t)) * HD + d;
                    psplit(v00, v01, hh, ll);
                    *(uint32_t*)(ohi + o) = hh; *(uint32_t*)(olo + o) = ll;
                }
                {
                    int r1 = row0 + 8;
                    int b = r1 >> 11, t = r1 & 2047;
                    size_t o = ((size_t)((b * H_ + h) * T_ + t)) * HD + d;
                    psplit(v10, v11, hh, ll);
                    *(uint32_t*)(ohi + o) = hh; *(uint32_t*)(olo + o) = ll;
                }
            } else {       // V transposed [B,H,hd,T]
                int b = row0 >> 11, t = row0 & 2047;
                int bhh = b * H_ + h;
                size_t base0 = ((size_t)(bhh * HD + d)) * T_;
                size_t base1 = ((size_t)(bhh * HD + d + 1)) * T_;
                __nv_bfloat16 h00 = __float2bfloat16_rn(v00);
                __nv_bfloat16 h01 = __float2bfloat16_rn(v01);
                __nv_bfloat16 h10 = __float2bfloat16_rn(v10);
                __nv_bfloat16 h11 = __float2bfloat16_rn(v11);
                ohi[base0 + t]     = h00;
                ohi[base1 + t]     = h01;
                ohi[base0 + t + 8] = h10;
                ohi[base1 + t + 8] = h11;
                olo[base0 + t]     = __float2bfloat16_rn(v00 - __bfloat162float(h00));
                olo[base1 + t]     = __float2bfloat16_rn(v01 - __bfloat162float(h01));
                olo[base0 + t + 8] = __float2bfloat16_rn(v10 - __bfloat162float(h10));
                olo[base1 + t + 8] = __float2bfloat16_rn(v11 - __bfloat162float(h11));
            }
        }
    }
}

// ---------- O-projection: fp32 row-major output ----------
__global__ __launch_bounds__(256, 2) void gemm_out(
    const __nv_bfloat16* __restrict__ Ahi, const __nv_bfloat16* __restrict__ Alo,
    const __nv_bfloat16* __restrict__ Whi, const __nv_bfloat16* __restrict__ Wlo,
    const float* __restrict__ bias, float* __restrict__ out)
{
    extern __shared__ __align__(16) char smem[];
    const uint32_t sbase = smem_u32(smem);
    const int tid = threadIdx.x;
    const int bm  = blockIdx.y * 128;
    const int bn  = blockIdx.x * 128;

    float acc[2][8][4];
    #pragma unroll
    for (int mi = 0; mi < 2; mi++)
        #pragma unroll
        for (int ni = 0; ni < 8; ni++)
            #pragma unroll
            for (int t = 0; t < 4; t++) acc[mi][ni][t] = 0.f;

    gemm_mainloop(sbase, Ahi, Alo, Whi, Wlo, bm, bn, tid, acc);

    const int lane = tid & 31;
    const int w    = tid >> 5;
    const int wm0  = (w & 3) * 32;
    const int wn0  = (w >> 2) * 64;

    #pragma unroll
    for (int mi = 0; mi < 2; mi++) {
        #pragma unroll
        for (int ni = 0; ni < 8; ni++) {
            int row0 = bm + wm0 + mi * 16 + (lane >> 2);
            int col  = bn + wn0 + ni * 8 + (lane & 3) * 2;
            float b0 = bias[col], b1 = bias[col + 1];
            float2 a; a.x = acc[mi][ni][0] + b0; a.y = acc[mi][ni][1] + b1;
            float2 c; c.x = acc[mi][ni][2] + b0; c.y = acc[mi][ni][3] + b1;
            *(float2*)&out[(size_t)row0 * C_ + col]       = a;
            *(float2*)&out[(size_t)(row0 + 8) * C_ + col] = c;
        }
    }
}

// =============================================================================
// Tensor-core flash attention (causal). Longest q-tiles first; single-sync
// double-buffered KV pipeline.
// =============================================================================
constexpr int ARS       = 72;
constexpr int QS_BYTES  = 128 * ARS * 2;
constexpr int KVT_BYTES = 64 * ARS * 2;
constexpr int ATT_SMEM  = 2 * QS_BYTES + 2 * 4 * KVT_BYTES;

__device__ __forceinline__ void att_load_kv(
    uint32_t sKh, uint32_t sKl, uint32_t sVh, uint32_t sVl,
    const __nv_bfloat16* __restrict__ khi, const __nv_bfloat16* __restrict__ klo,
    const __nv_bfloat16* __restrict__ vthi, const __nv_bfloat16* __restrict__ vtlo,
    int bh, int k0, int tid)
{
    #pragma unroll
    for (int it = 0; it < 2; it++) {
        int id  = tid + it * 256;
        int row = id >> 3;
        int ch  = id & 7;
        uint32_t so = (uint32_t)(row * (ARS * 2) + ch * 16);
        size_t goK = ((size_t)(bh * T_ + k0 + row) * HD + ch * 8) * 2;
        cp_async16(sKh + so, (const char*)khi + goK);
        cp_async16(sKl + so, (const char*)klo + goK);
        size_t goV = ((size_t)(bh * HD + row) * T_ + k0 + ch * 8) * 2;
        cp_async16(sVh + so, (const char*)vthi + goV);
        cp_async16(sVl + so, (const char*)vtlo + goV);
    }
}

__global__ __launch_bounds__(256, 1) void attn_tc(
    const __nv_bfloat16* __restrict__ qhi, const __nv_bfloat16* __restrict__ qlo,
    const __nv_bfloat16* __restrict__ khi, const __nv_bfloat16* __restrict__ klo,
    const __nv_bfloat16* __restrict__ vthi, const __nv_bfloat16* __restrict__ vtlo,
    __nv_bfloat16* __restrict__ out_hi, __nv_bfloat16* __restrict__ out_lo)
{
    extern __shared__ __align__(16) char smem[];
    const uint32_t sb  = smem_u32(smem);
    const uint32_t sQh = sb, sQl = sb + QS_BYTES;
    const int tid  = threadIdx.x;
    const int lane = tid & 31;
    const int w    = tid >> 5;
    const int bh   = blockIdx.x;
    const int qi   = (int)gridDim.y - 1 - (int)blockIdx.y;  // longest first
    const int q0   = qi * 128;
    const int ktmax = 2 * qi + 1;
    const float SC = 0.18033688011112042f;   // hd^-0.5 * log2(e)

    #pragma unroll
    for (int it = 0; it < 4; it++) {
        int id  = tid + it * 256;
        int row = id >> 3;
        int ch  = id & 7;
        uint32_t so = (uint32_t)(row * (ARS * 2) + ch * 16);
        size_t go = ((size_t)(bh * T_ + q0 + row) * HD + ch * 8) * 2;
        cp_async16(sQh + so, (const char*)qhi + go);
        cp_async16(sQl + so, (const char*)qlo + go);
    }
    {
        uint32_t skv = sb + 2 * QS_BYTES;
        att_load_kv(skv, skv + KVT_BYTES, skv + 2 * KVT_BYTES, skv + 3 * KVT_BYTES,
                    khi, klo, vthi, vtlo, bh, 0, tid);
    }
    CP_ASYNC_COMMIT();

    float o[8][4];
    #pragma unroll
    for (int n = 0; n < 8; n++)
        #pragma unroll
        for (int t = 0; t < 4; t++) o[n][t] = 0.f;
    float m0 = -1e30f, m1 = -1e30f, l0 = 0.f, l1 = 0.f;
    uint32_t qfh[4][4], qfl[4][4];

    const int rlo_base = q0 + w * 16 + (lane >> 2);

    for (int kt = 0; kt <= ktmax; kt++) {
        const int s = kt & 1;
        CP_ASYNC_WAIT(0);
        __syncthreads();   // stage s data visible; stage s^1 readers (kt-1) done

        if (kt == 0) {
            #pragma unroll
            for (int kc = 0; kc < 4; kc++) {
                uint32_t off = (uint32_t)((w * 16 + (lane & 15)) * (ARS * 2)
                                          + kc * 32 + ((lane >> 4) << 4));
                ldsm_x4(sQh + off, qfh[kc]);
                ldsm_x4(sQl + off, qfl[kc]);
            }
        }

        if (kt + 1 <= ktmax) {
            uint32_t skv = sb + 2 * QS_BYTES + (uint32_t)(s ^ 1) * 4 * KVT_BYTES;
            att_load_kv(skv, skv + KVT_BYTES, skv + 2 * KVT_BYTES, skv + 3 * KVT_BYTES,
                        khi, klo, vthi, vtlo, bh, (kt + 1) * 64, tid);
            CP_ASYNC_COMMIT();
        }

        bool active = (kt * 64 <= q0 + w * 16 + 15);

        if (active) {
            const uint32_t skv = sb + 2 * QS_BYTES + (uint32_t)s * 4 * KVT_BYTES;
            const uint32_t sKh = skv, sKl = skv + KVT_BYTES;
            const uint32_t sVh = skv + 2 * KVT_BYTES, sVl = skv + 3 * KVT_BYTES;

            float sv[8][4];
            #pragma unroll
            for (int n = 0; n < 8; n++)
                #pragma unroll
                for (int t = 0; t < 4; t++) sv[n][t] = 0.f;

            #pragma unroll
            for (int kc = 0; kc < 4; kc++) {
                uint32_t kh[8][2], kl[8][2];
                #pragma unroll
                for (int p = 0; p < 4; p++) {
                    uint32_t off = (uint32_t)((p * 16 + (lane & 7) + ((lane >> 4) & 1) * 8)
                                              * (ARS * 2) + kc * 32 + ((lane >> 3) & 1) * 16);
                    uint32_t tmp[4];
                    ldsm_x4(sKh + off, tmp);
                    kh[2 * p][0] = tmp[0]; kh[2 * p][1] = tmp[1];
                    kh[2 * p + 1][0] = tmp[2]; kh[2 * p + 1][1] = tmp[3];
                    ldsm_x4(sKl + off, tmp);
                    kl[2 * p][0] = tmp[0]; kl[2 * p][1] = tmp[1];
                    kl[2 * p + 1][0] = tmp[2]; kl[2 * p + 1][1] = tmp[3];
                }
                #pragma unroll
                for (int n = 0; n < 8; n++) mma_bf16(sv[n], qfh[kc], kh[n]);
                #pragma unroll
                for (int n = 0; n < 8; n++) mma_bf16(sv[n], qfh[kc], kl[n]);
                #pragma unroll
                for (int n = 0; n < 8; n++) mma_bf16(sv[n], qfl[kc], kh[n]);
            }

            const int rlo = rlo_base;
            const int rhi = rlo + 8;
            const bool needmask = (kt * 64 + 63 > q0 + w * 16);
            float mx0 = m0, mx1 = m1;
            #pragma unroll
            for (int n = 0; n < 8; n++) {
                int j = kt * 64 + n * 8 + (lane & 3) * 2;
                sv[n][0] *= SC; sv[n][1] *= SC; sv[n][2] *= SC; sv[n][3] *= SC;
                if (needmask) {
                    if (j     > rlo) sv[n][0] = -1e30f;
                    if (j + 1 > rlo) sv[n][1] = -1e30f;
                    if (j     > rhi) sv[n][2] = -1e30f;
                    if (j + 1 > rhi) sv[n][3] = -1e30f;
                }
                mx0 = fmaxf(mx0, fmaxf(sv[n][0], sv[n][1]));
                mx1 = fmaxf(mx1, fmaxf(sv[n][2], sv[n][3]));
            }
            mx0 = fmaxf(mx0, __shfl_xor_sync(0xffffffffu, mx0, 1));
            mx0 = fmaxf(mx0, __shfl_xor_sync(0xffffffffu, mx0, 2));
            mx1 = fmaxf(mx1, __shfl_xor_sync(0xffffffffu, mx1, 1));
            mx1 = fmaxf(mx1, __shfl_xor_sync(0xffffffffu, mx1, 2));
            const float a0 = ex2f(m0 - mx0);
            const float a1 = ex2f(m1 - mx1);
            m0 = mx0; m1 = mx1;

            float sum0 = 0.f, sum1 = 0.f;
            #pragma unroll
            for (int n = 0; n < 8; n++) {
                sv[n][0] = ex2f(sv[n][0] - mx0);
                sv[n][1] = ex2f(sv[n][1] - mx0);
                sv[n][2] = ex2f(sv[n][2] - mx1);
                sv[n][3] = ex2f(sv[n][3] - mx1);
                sum0 += sv[n][0] + sv[n][1];
                sum1 += sv[n][2] + sv[n][3];
            }
            l0 = l0 * a0 + sum0;
            l1 = l1 * a1 + sum1;
            #pragma unroll
            for (int n = 0; n < 8; n++) {
                o[n][0] *= a0; o[n][1] *= a0; o[n][2] *= a1; o[n][3] *= a1;
            }

            uint32_t ph[4][4], pl[4][4];
            #pragma unroll
            for (int kc = 0; kc < 4; kc++) {
                psplit(sv[2 * kc][0],     sv[2 * kc][1],     ph[kc][0], pl[kc][0]);
                psplit(sv[2 * kc][2],     sv[2 * kc][3],     ph[kc][1], pl[kc][1]);
                psplit(sv[2 * kc + 1][0], sv[2 * kc + 1][1], ph[kc][2], pl[kc][2]);
                psplit(sv[2 * kc + 1][2], sv[2 * kc + 1][3], ph[kc][3], pl[kc][3]);
            }

            #pragma unroll
            for (int kc = 0; kc < 4; kc++) {
                uint32_t vh[8][2], vl[8][2];
                #pragma unroll
                for (int p = 0; p < 4; p++) {
                    uint32_t off = (uint32_t)((p * 16 + (lane & 7) + ((lane >> 4) & 1) * 8)
                                              * (ARS * 2) + kc * 32 + ((lane >> 3) & 1) * 16);
                    uint32_t tmp[4];
                    ldsm_x4(sVh + off, tmp);
                    vh[2 * p][0] = tmp[0]; vh[2 * p][1] = tmp[1];
                    vh[2 * p + 1][0] = tmp[2]; vh[2 * p + 1][1] = tmp[3];
                    ldsm_x4(sVl + off, tmp);
                    vl[2 * p][0] = tmp[0]; vl[2 * p][1] = tmp[1];
                    vl[2 * p + 1][0] = tmp[2]; vl[2 * p + 1][1] = tmp[3];
                }
                #pragma unroll
                for (int n = 0; n < 8; n++) mma_bf16(o[n], ph[kc], vh[n]);
                #pragma unroll
                for (int n = 0; n < 8; n++) mma_bf16(o[n], ph[kc], vl[n]);
                #pragma unroll
                for (int n = 0; n < 8; n++) mma_bf16(o[n], pl[kc], vh[n]);
            }
        }
        __syncthreads();   // all warps done reading stage s before it reloads
    }

    l0 += __shfl_xor_sync(0xffffffffu, l0, 1);
    l0 += __shfl_xor_sync(0xffffffffu, l0, 2);
    l1 += __shfl_xor_sync(0xffffffffu, l1, 1);
    l1 += __shfl_xor_sync(0xffffffffu, l1, 2);
    const float inv0 = 1.f / l0;
    const float inv1 = 1.f / l1;

    const int b = bh >> 4, h = bh & 15;
    const int t0 = q0 + w * 16 + (lane >> 2);
    const int t1 = t0 + 8;
    #pragma unroll
    for (int n = 0; n < 8; n++) {
        int d = n * 8 + (lane & 3) * 2;
        uint32_t hh, ll;
        size_t o0 = ((size_t)(b * T_ + t0)) * C_ + h * HD + d;
        psplit(o[n][0] * inv0, o[n][1] * inv0, hh, ll);
        *(uint32_t*)(out_hi + o0) = hh;
        *(uint32_t*)(out_lo + o0) = ll;
        size_t o1 = ((size_t)(b * T_ + t1)) * C_ + h * HD + d;
        psplit(o[n][2] * inv1, o[n][3] * inv1, hh, ll);
        *(uint32_t*)(out_hi + o1) = hh;
        *(uint32_t*)(out_lo + o1) = ll;
    }
}

// =============================================================================
extern "C" void kernel_launch(void* const* d_in, const int* in_sizes, int n_in,
                              void* d_out, int out_size)
{
    (void)in_sizes; (void)n_in; (void)out_size;
    const float* x  = (const float*)d_in[0];
    const float* wq = (const float*)d_in[1];
    const float* bq = (const float*)d_in[2];
    const float* wk = (const float*)d_in[3];
    const float* bk = (const float*)d_in[4];
    const float* wv = (const float*)d_in[5];
    const float* bv = (const float*)d_in[6];
    const float* wo = (const float*)d_in[7];
    const float* bo = (const float*)d_in[8];
    float* out = (float*)d_out;

    __nv_bfloat16 *ahi, *alo, *whi, *wlo;
    __nv_bfloat16 *qhi, *qlo, *khi, *klo, *vthi, *vtlo;
    cudaGetSymbolAddress((void**)&ahi,  g_ahi);
    cudaGetSymbolAddress((void**)&alo,  g_alo);
    cudaGetSymbolAddress((void**)&whi,  g_whi);
    cudaGetSymbolAddress((void**)&wlo,  g_wlo);
    cudaGetSymbolAddress((void**)&qhi,  g_qhi);
    cudaGetSymbolAddress((void**)&qlo,  g_qlo);
    cudaGetSymbolAddress((void**)&khi,  g_khi);
    cudaGetSymbolAddress((void**)&klo,  g_klo);
    cudaGetSymbolAddress((void**)&vthi, g_vthi);
    cudaGetSymbolAddress((void**)&vtlo, g_vtlo);

    const int nW = C_ * C_;

    // one fused split launch: x + 4 weight matrices
    split_all<<<12288, 256>>>(x, wq, wk, wv, wo, ahi, alo, whi, wlo);

    cudaFuncSetAttribute(gemm_qkv, cudaFuncAttributeMaxDynamicSharedMemorySize, GEMM_SMEM);
    cudaFuncSetAttribute(gemm_out, cudaFuncAttributeMaxDynamicSharedMemorySize, GEMM_SMEM);
    cudaFuncSetAttribute(attn_tc,  cudaFuncAttributeMaxDynamicSharedMemorySize, ATT_SMEM);

    // fused QKV projections (z = 0,1,2)
    gemm_qkv<<<dim3(C_ / 128, M_ / 128, 3), 256, GEMM_SMEM>>>(
        ahi, alo, whi, wlo, bq, bk, bv, qhi, qlo, khi, klo, vthi, vtlo);

    // attention overwrites ahi/alo with split attention output
    attn_tc<<<dim3(B_ * H_, T_ / 128), 256, ATT_SMEM>>>(qhi, qlo, khi, klo,
                                                        vthi, vtlo, ahi, alo);

    gemm_out<<<dim3(C_ / 128, M_ / 128), 256, GEMM_SMEM>>>(
        ahi, alo, whi + 3 * nW, wlo + 3 * nW, bo, out);
}